// round 8
// baseline (speedup 1.0000x reference)
#include <cuda_runtime.h>
#include <cuda_bf16.h>
#include <cstdint>
#include <math.h>

#define EPS 1e-5f

// ---------------- scratch (device globals) ----------------
__device__ float g_bufA[67108864];               // GEMM1 H outputs (max 131072x512)
__device__ float g_bufB[16777216];               // GEMM2 outputs (max 32768x512)
__device__ float g_bufC[67108864];               // concat buffers (fp32)
__device__ __nv_bfloat16 g_whi[4194304];         // weight hi planes (all 8 GEMMs)
__device__ __nv_bfloat16 g_wlo[4194304];         // weight lo planes
__device__ float g_sum[1024];
__device__ float g_sumsq[1024];
__device__ float g_scale[1024];
__device__ float g_shift[1024];

// ---------------- PTX helpers ----------------
__device__ __forceinline__ uint32_t smem_u32(const void* p) {
    uint32_t a;
    asm("{ .reg .u64 t; cvta.to.shared.u64 t, %1; cvt.u32.u64 %0, t; }" : "=r"(a) : "l"(p));
    return a;
}
__device__ __forceinline__ void cp16(uint32_t sdst, const void* gsrc) {
    asm volatile("cp.async.cg.shared.global [%0], [%1], 16;" :: "r"(sdst), "l"(gsrc));
}
#define CP_COMMIT() asm volatile("cp.async.commit_group;" ::: "memory")
#define CP_WAIT0()  asm volatile("cp.async.wait_group 0;" ::: "memory")

__device__ __forceinline__ void ldsm_x4(uint32_t* r, uint32_t addr) {
    asm volatile("ldmatrix.sync.aligned.m8n8.x4.shared.b16 {%0,%1,%2,%3}, [%4];"
                 : "=r"(r[0]), "=r"(r[1]), "=r"(r[2]), "=r"(r[3]) : "r"(addr));
}
__device__ __forceinline__ void ldsm_x4_t(uint32_t* r, uint32_t addr) {
    asm volatile("ldmatrix.sync.aligned.m8n8.x4.trans.shared.b16 {%0,%1,%2,%3}, [%4];"
                 : "=r"(r[0]), "=r"(r[1]), "=r"(r[2]), "=r"(r[3]) : "r"(addr));
}
__device__ __forceinline__ void mma16816(float* d, const uint32_t* a, uint32_t b0, uint32_t b1) {
    asm volatile("mma.sync.aligned.m16n8k16.row.col.f32.bf16.bf16.f32 "
                 "{%0,%1,%2,%3}, {%4,%5,%6,%7}, {%8,%9}, {%0,%1,%2,%3};"
                 : "+f"(d[0]), "+f"(d[1]), "+f"(d[2]), "+f"(d[3])
                 : "r"(a[0]), "r"(a[1]), "r"(a[2]), "r"(a[3]), "r"(b0), "r"(b1));
}

// fp32x4 -> hi/lo bf16x4 (8B each)
__device__ __forceinline__ void split4s(float4 v, char* hp, char* lp) {
    __nv_bfloat162 h01 = __floats2bfloat162_rn(v.x, v.y);
    __nv_bfloat162 h23 = __floats2bfloat162_rn(v.z, v.w);
    float2 f01 = __bfloat1622float2(h01);
    float2 f23 = __bfloat1622float2(h23);
    __nv_bfloat162 l01 = __floats2bfloat162_rn(v.x - f01.x, v.y - f01.y);
    __nv_bfloat162 l23 = __floats2bfloat162_rn(v.z - f23.x, v.w - f23.y);
    uint2 hv, lv;
    hv.x = *reinterpret_cast<uint32_t*>(&h01);
    hv.y = *reinterpret_cast<uint32_t*>(&h23);
    lv.x = *reinterpret_cast<uint32_t*>(&l01);
    lv.y = *reinterpret_cast<uint32_t*>(&l23);
    *reinterpret_cast<uint2*>(hp) = hv;
    *reinterpret_cast<uint2*>(lp) = lv;
}

// ---------------- elementwise kernels ----------------
__global__ void zero_stats_kernel(int n) {
    int i = blockIdx.x * blockDim.x + threadIdx.x;
    if (i < n) { g_sum[i] = 0.f; g_sumsq[i] = 0.f; }
}

__global__ void finalize_stats_kernel(const float* __restrict__ gamma,
                                      const float* __restrict__ beta,
                                      int N, float invM) {
    int i = blockIdx.x * blockDim.x + threadIdx.x;
    if (i >= N) return;
    float mu  = g_sum[i] * invM;
    float var = g_sumsq[i] * invM - mu * mu;
    float sc  = gamma[i] * rsqrtf(var + EPS);
    g_scale[i] = sc;
    g_shift[i] = beta[i] - mu * sc;
}

// W (K,N) fp32 -> bf16 hi/lo planes, same layout
__global__ void wsplit_kernel(const float* __restrict__ W,
                              __nv_bfloat16* __restrict__ hi, __nv_bfloat16* __restrict__ lo,
                              long long total4) {
    for (long long i = (long long)blockIdx.x * blockDim.x + threadIdx.x;
         i < total4; i += (long long)gridDim.x * blockDim.x) {
        float4 v = *(const float4*)(W + i * 4);
        split4s(v, (char*)(hi + i * 4), (char*)(lo + i * 4));
    }
}

__global__ void build_cat_kernel(const float* __restrict__ left,
                                 const float* __restrict__ right,
                                 const int* __restrict__ idx,
                                 float* __restrict__ out,
                                 int rows, int Cl, int Cr,
                                 int outRowsPerBatch, int srcRowsPerBatch) {
    int cols = Cl + Cr;
    int c4n = cols >> 2;
    long long t = (long long)blockIdx.x * blockDim.x + threadIdx.x;
    long long total = (long long)rows * c4n;
    if (t >= total) return;
    int row = (int)(t / c4n);
    int c4 = (int)(t % c4n) * 4;
    float4 v;
    if (c4 < Cl) {
        v = *(const float4*)(left + (size_t)row * Cl + c4);
    } else {
        int b = row / outRowsPerBatch;
        int src = b * srcRowsPerBatch + idx[row];
        v = *(const float4*)(right + (size_t)src * Cr + (c4 - Cl));
    }
    *(float4*)(out + (size_t)row * cols + c4) = v;
}

// ---------------- HMMA GEMM ----------------
// C = f(A) @ W + bias.  A (M,K) fp32; W pre-split bf16 planes (K,N).
// BM=128, BN=256, BK=32; 256 threads (8 warps, 2x4), warp tile 64x64.
// 3-product split-bf16; W via cp.async, A converted in-kernel.
template <bool NORM, bool STATS>
__global__ __launch_bounds__(256, 1)
void hmma_gemm_kernel(const float* __restrict__ A,
                      const __nv_bfloat16* __restrict__ Wh, const __nv_bfloat16* __restrict__ Wl,
                      const float* __restrict__ bias, float* __restrict__ C,
                      int M, int N, int K) {
    constexpr int A_STR = 80;                 // bytes per A smem row (32 bf16 + pad)
    constexpr int W_STR = 528;                // bytes per W smem row (256 bf16 + pad)
    constexpr int A_PLANE = 128 * A_STR;      // 10240
    constexpr int W_PLANE = 32 * W_STR;       // 16896
    constexpr int OFF_AH = 0;
    constexpr int OFF_AL = A_PLANE;
    constexpr int OFF_WH = 2 * A_PLANE;
    constexpr int OFF_WL = 2 * A_PLANE + W_PLANE;
    constexpr int STAGE = 2 * A_PLANE + 2 * W_PLANE;  // 54272

    extern __shared__ char sm[];
    const uint32_t smb = smem_u32(sm);

    const int tid = threadIdx.x;
    const int wid = tid >> 5;
    const int lane = tid & 31;
    const int warp_m = (wid >> 2) * 64;       // 0 or 64
    const int warp_n = (wid & 3) * 64;        // 0,64,128,192
    const int bm0 = blockIdx.y * 128;
    const int bn0 = blockIdx.x * 256;
    const int T = K >> 5;

    // A fp32 LDG mapping: 128x32 = 1024 float4, 4 per thread
    int a_row[4], a_c[4];
    uint32_t a_soff[4];
#pragma unroll
    for (int i = 0; i < 4; i++) {
        int idx = tid + (i << 8);
        a_row[i] = idx >> 3;
        a_c[i] = (idx & 7) << 2;
        a_soff[i] = a_row[i] * A_STR + a_c[i] * 2;
    }
    // W cp.async mapping: per plane 32 rows x 32 chunks(16B) = 1024 chunks, 4 per thread
    int wRow[4], wCol[4];
    uint32_t wS[4];
#pragma unroll
    for (int i = 0; i < 4; i++) {
        int c = tid + (i << 8);
        wRow[i] = c >> 5;
        wCol[i] = (c & 31) * 8;               // bf16 column
        wS[i] = wRow[i] * W_STR + (c & 31) * 16;
    }

    // ldmatrix offsets (stage-relative)
    uint32_t a_off[4], b_off[4];
#pragma unroll
    for (int mt = 0; mt < 4; mt++)
        a_off[mt] = (uint32_t)((warp_m + mt * 16 + (lane & 15)) * A_STR + ((lane >> 4) << 3) * 2);
#pragma unroll
    for (int np = 0; np < 4; np++)
        b_off[np] = (uint32_t)((lane & 15) * W_STR + (warp_n + np * 16 + ((lane >> 4) << 3)) * 2);

    float acc[4][8][4];
#pragma unroll
    for (int mt = 0; mt < 4; mt++)
#pragma unroll
        for (int nt = 0; nt < 8; nt++)
#pragma unroll
            for (int q = 0; q < 4; q++) acc[mt][nt][q] = 0.f;

    float4 ar[4];

    // ---- prologue: W cp stage0, A ldg+convert stage0 ----
    {
#pragma unroll
        for (int i = 0; i < 4; i++) {
            size_t gw = (size_t)wRow[i] * N + bn0 + wCol[i];
            cp16(smb + OFF_WH + wS[i], Wh + gw);
            cp16(smb + OFF_WL + wS[i], Wl + gw);
        }
        CP_COMMIT();
#pragma unroll
        for (int i = 0; i < 4; i++)
            ar[i] = *(const float4*)(A + (size_t)(bm0 + a_row[i]) * K + a_c[i]);
#pragma unroll
        for (int i = 0; i < 4; i++) {
            float4 v = ar[i];
            if (NORM) {
                float4 sc = *(const float4*)(g_scale + a_c[i]);
                float4 sh = *(const float4*)(g_shift + a_c[i]);
                v.x = fmaxf(v.x * sc.x + sh.x, 0.f);
                v.y = fmaxf(v.y * sc.y + sh.y, 0.f);
                v.z = fmaxf(v.z * sc.z + sh.z, 0.f);
                v.w = fmaxf(v.w * sc.w + sh.w, 0.f);
            }
            split4s(v, sm + OFF_AH + a_soff[i], sm + OFF_AL + a_soff[i]);
        }
        CP_WAIT0();
    }
    __syncthreads();

    for (int t = 0; t < T; t++) {
        const int s = t & 1;
        const uint32_t sbase = smb + s * STAGE;
        const bool has_next = (t + 1 < T);
        const int k0n = (t + 1) << 5;

        if (has_next) {
            uint32_t nb = smb + (s ^ 1) * STAGE;
#pragma unroll
            for (int i = 0; i < 4; i++) {
                size_t gw = (size_t)(k0n + wRow[i]) * N + bn0 + wCol[i];
                cp16(nb + OFF_WH + wS[i], Wh + gw);
                cp16(nb + OFF_WL + wS[i], Wl + gw);
            }
            CP_COMMIT();
#pragma unroll
            for (int i = 0; i < 4; i++)
                ar[i] = *(const float4*)(A + (size_t)(bm0 + a_row[i]) * K + k0n + a_c[i]);
        }

#pragma unroll
        for (int ks = 0; ks < 2; ks++) {
            uint32_t ah[4][4], al[4][4];
#pragma unroll
            for (int mt = 0; mt < 4; mt++) {
                ldsm_x4(ah[mt], sbase + OFF_AH + a_off[mt] + ks * 32);
                ldsm_x4(al[mt], sbase + OFF_AL + a_off[mt] + ks * 32);
            }
#pragma unroll
            for (int np = 0; np < 4; np++) {
                uint32_t bh[4], bl[4];
                ldsm_x4_t(bh, sbase + OFF_WH + b_off[np] + ks * (16 * W_STR));
                ldsm_x4_t(bl, sbase + OFF_WL + b_off[np] + ks * (16 * W_STR));
#pragma unroll
                for (int mt = 0; mt < 4; mt++) {
#pragma unroll
                    for (int half = 0; half < 2; half++) {
                        int nt = np * 2 + half;
                        mma16816(acc[mt][nt], ah[mt], bh[half * 2], bh[half * 2 + 1]);
                        mma16816(acc[mt][nt], ah[mt], bl[half * 2], bl[half * 2 + 1]);
                        mma16816(acc[mt][nt], al[mt], bh[half * 2], bh[half * 2 + 1]);
                    }
                }
            }
        }

        if (has_next) {
            char* nb = sm + (s ^ 1) * STAGE;
#pragma unroll
            for (int i = 0; i < 4; i++) {
                float4 v = ar[i];
                if (NORM) {
                    float4 sc = *(const float4*)(g_scale + k0n + a_c[i]);
                    float4 sh = *(const float4*)(g_shift + k0n + a_c[i]);
                    v.x = fmaxf(v.x * sc.x + sh.x, 0.f);
                    v.y = fmaxf(v.y * sc.y + sh.y, 0.f);
                    v.z = fmaxf(v.z * sc.z + sh.z, 0.f);
                    v.w = fmaxf(v.w * sc.w + sh.w, 0.f);
                }
                split4s(v, nb + OFF_AH + a_soff[i], nb + OFF_AL + a_soff[i]);
            }
            CP_WAIT0();
        }
        __syncthreads();
    }

    // ---- epilogue: bias + store (+ column stats) ----
    // nt -> col: c0 = bn0 + warp_n + (nt>>1)*16 + (nt&1)*8 + (lane&3)*2
#pragma unroll
    for (int nt = 0; nt < 8; nt++) {
        int c0 = bn0 + warp_n + (nt >> 1) * 16 + (nt & 1) * 8 + (lane & 3) * 2;
        float b0 = bias[c0], b1 = bias[c0 + 1];
        float s0 = 0.f, s1 = 0.f, q0 = 0.f, q1 = 0.f;
#pragma unroll
        for (int mt = 0; mt < 4; mt++) {
            int r0 = bm0 + warp_m + mt * 16 + (lane >> 2);
            float v0 = acc[mt][nt][0] + b0, v1 = acc[mt][nt][1] + b1;
            float v2 = acc[mt][nt][2] + b0, v3 = acc[mt][nt][3] + b1;
            float2 p0; p0.x = v0; p0.y = v1;
            float2 p1; p1.x = v2; p1.y = v3;
            *(float2*)(C + (size_t)r0 * N + c0) = p0;
            *(float2*)(C + (size_t)(r0 + 8) * N + c0) = p1;
            if (STATS) {
                s0 += v0 + v2; s1 += v1 + v3;
                q0 += v0 * v0 + v2 * v2; q1 += v1 * v1 + v3 * v3;
            }
        }
        if (STATS) {
#pragma unroll
            for (int off = 4; off < 32; off <<= 1) {
                s0 += __shfl_xor_sync(0xFFFFFFFFu, s0, off);
                s1 += __shfl_xor_sync(0xFFFFFFFFu, s1, off);
                q0 += __shfl_xor_sync(0xFFFFFFFFu, q0, off);
                q1 += __shfl_xor_sync(0xFFFFFFFFu, q1, off);
            }
            if ((lane >> 2) == 0) {
                atomicAdd(&g_sum[c0], s0);
                atomicAdd(&g_sum[c0 + 1], s1);
                atomicAdd(&g_sumsq[c0], q0);
                atomicAdd(&g_sumsq[c0 + 1], q1);
            }
        }
    }
}

// ---------------- host orchestration ----------------
static const int GEMM_SMEM = 2 * 54272;   // 108544

static __nv_bfloat16 *s_whi, *s_wlo;
static float *s_bufA, *s_bufB, *s_bufC;

template <bool NORM, bool STATS>
static void run_gemm(const float* A, size_t woff, const float* bias, float* C,
                     int M, int N, int K) {
    dim3 grid(N / 256, M / 128);
    hmma_gemm_kernel<NORM, STATS><<<grid, 256, GEMM_SMEM>>>(A, s_whi + woff, s_wlo + woff,
                                                            bias, C, M, N, K);
}

extern "C" void kernel_launch(void* const* d_in, const int* in_sizes, int n_in,
                              void* d_out, int out_size) {
    const float* f0 = (const float*)d_in[0];
    const float* f1 = (const float*)d_in[1];
    const float* f2 = (const float*)d_in[2];
    const float* up0_w1 = (const float*)d_in[3];
    const float* up0_b1 = (const float*)d_in[4];
    const float* up0_g  = (const float*)d_in[5];
    const float* up0_be = (const float*)d_in[6];
    const float* up0_w2 = (const float*)d_in[7];
    const float* up0_b2 = (const float*)d_in[8];
    const float* up1_w1 = (const float*)d_in[9];
    const float* up1_b1 = (const float*)d_in[10];
    const float* up1_g  = (const float*)d_in[11];
    const float* up1_be = (const float*)d_in[12];
    const float* up1_w2 = (const float*)d_in[13];
    const float* up1_b2 = (const float*)d_in[14];
    const float* skip0_w1 = (const float*)d_in[15];
    const float* skip0_b1 = (const float*)d_in[16];
    const float* skip0_g  = (const float*)d_in[17];
    const float* skip0_be = (const float*)d_in[18];
    const float* skip0_w2 = (const float*)d_in[19];
    const float* skip0_b2 = (const float*)d_in[20];
    const float* skip1_w1 = (const float*)d_in[21];
    const float* skip1_b1 = (const float*)d_in[22];
    const float* skip1_g  = (const float*)d_in[23];
    const float* skip1_be = (const float*)d_in[24];
    const float* skip1_w2 = (const float*)d_in[25];
    const float* skip1_b2 = (const float*)d_in[26];
    const int*   pool0 = (const int*)d_in[27];
    const int*   pool1 = (const int*)d_in[28];
    float* out = (float*)d_out;

    cudaGetSymbolAddress((void**)&s_bufA, g_bufA);
    cudaGetSymbolAddress((void**)&s_bufB, g_bufB);
    cudaGetSymbolAddress((void**)&s_bufC, g_bufC);
    cudaGetSymbolAddress((void**)&s_whi, g_whi);
    cudaGetSymbolAddress((void**)&s_wlo, g_wlo);

    cudaFuncSetAttribute(hmma_gemm_kernel<false, true>, cudaFuncAttributeMaxDynamicSharedMemorySize, GEMM_SMEM);
    cudaFuncSetAttribute(hmma_gemm_kernel<true, false>, cudaFuncAttributeMaxDynamicSharedMemorySize, GEMM_SMEM);

    const int B = 4;
    const int N0 = 32768, N1 = 8192, N2 = 2048;
    const int C0 = 256, C1 = 512, C2 = 1024;
    const int M_u1 = B * N2, M_s1 = B * N1, M_s0 = B * N0;

    // weight plane offsets (K,N) layout
    const size_t O_U1W1 = 0;
    const size_t O_U1W2 = 1048576;
    const size_t O_S1W1 = 1572864;
    const size_t O_S1W2 = 2621440;
    const size_t O_U0W1 = 3145728;
    const size_t O_U0W2 = 3407872;
    const size_t O_S0W1 = 3538944;
    const size_t O_S0W2 = 3801088;

    // ---- up1 MLP: f2 (8192,1024) -> 1024 -> 512 ----
    zero_stats_kernel<<<4, 256>>>(1024);
    wsplit_kernel<<<512, 256>>>(up1_w1, s_whi + O_U1W1, s_wlo + O_U1W1, (long long)C2 * C2 / 4);
    wsplit_kernel<<<512, 256>>>(up1_w2, s_whi + O_U1W2, s_wlo + O_U1W2, (long long)C2 * C1 / 4);
    run_gemm<false, true>(f2, O_U1W1, up1_b1, s_bufA, M_u1, C2, C2);     // profiled slot
    finalize_stats_kernel<<<4, 256>>>(up1_g, up1_be, C2, 1.0f / M_u1);
    run_gemm<true, false>(s_bufA, O_U1W2, up1_b2, s_bufB, M_u1, C1, C2);

    // ---- gather pool1 + concat f1 -> bufC (32768,1024) ----
    {
        long long total = (long long)M_s1 * ((2 * C1) / 4);
        build_cat_kernel<<<(int)((total + 255) / 256), 256>>>(f1, s_bufB, pool1, s_bufC,
                                                              M_s1, C1, C1, N1, N2);
    }

    // ---- skip1 MLP: (32768,1024) -> 1024 -> 512 ----
    zero_stats_kernel<<<4, 256>>>(1024);
    wsplit_kernel<<<512, 256>>>(skip1_w1, s_whi + O_S1W1, s_wlo + O_S1W1, (long long)(2 * C1) * (2 * C1) / 4);
    wsplit_kernel<<<512, 256>>>(skip1_w2, s_whi + O_S1W2, s_wlo + O_S1W2, (long long)(2 * C1) * C1 / 4);
    run_gemm<false, true>(s_bufC, O_S1W1, skip1_b1, s_bufA, M_s1, 2 * C1, 2 * C1);
    finalize_stats_kernel<<<4, 256>>>(skip1_g, skip1_be, 2 * C1, 1.0f / M_s1);
    run_gemm<true, false>(s_bufA, O_S1W2, skip1_b2, s_bufB, M_s1, C1, 2 * C1);

    // ---- up0 MLP: (32768,512) -> 512 -> 256 ----
    zero_stats_kernel<<<2, 256>>>(512);
    wsplit_kernel<<<256, 256>>>(up0_w1, s_whi + O_U0W1, s_wlo + O_U0W1, (long long)C1 * C1 / 4);
    wsplit_kernel<<<256, 256>>>(up0_w2, s_whi + O_U0W2, s_wlo + O_U0W2, (long long)C1 * C0 / 4);
    run_gemm<false, true>(s_bufB, O_U0W1, up0_b1, s_bufA, M_s1, C1, C1);
    finalize_stats_kernel<<<2, 256>>>(up0_g, up0_be, C1, 1.0f / M_s1);
    run_gemm<true, false>(s_bufA, O_U0W2, up0_b2, s_bufB, M_s1, C0, C1);

    // ---- gather pool0 + concat f0 -> bufC (131072,512) ----
    {
        long long total = (long long)M_s0 * ((2 * C0) / 4);
        build_cat_kernel<<<(int)((total + 255) / 256), 256>>>(f0, s_bufB, pool0, s_bufC,
                                                              M_s0, C0, C0, N0, N1);
    }

    // ---- skip0 MLP: (131072,512) -> 512 -> 256 -> out ----
    zero_stats_kernel<<<2, 256>>>(512);
    wsplit_kernel<<<256, 256>>>(skip0_w1, s_whi + O_S0W1, s_wlo + O_S0W1, (long long)(2 * C0) * (2 * C0) / 4);
    wsplit_kernel<<<256, 256>>>(skip0_w2, s_whi + O_S0W2, s_wlo + O_S0W2, (long long)(2 * C0) * C0 / 4);
    run_gemm<false, true>(s_bufC, O_S0W1, skip0_b1, s_bufA, M_s0, 2 * C0, 2 * C0);
    finalize_stats_kernel<<<2, 256>>>(skip0_g, skip0_be, 2 * C0, 1.0f / M_s0);
    run_gemm<true, false>(s_bufA, O_S0W2, skip0_b2, out, M_s0, C0, 2 * C0);
}

// round 9
// speedup vs baseline: 1.0176x; 1.0176x over previous
#include <cuda_runtime.h>
#include <cuda_bf16.h>
#include <cstdint>
#include <math.h>

#define EPS 1e-5f

// ---------------- scratch (device globals) ----------------
__device__ float g_bufA[67108864];               // GEMM1 H outputs (max 131072x512)
__device__ float g_bufB[16777216];               // GEMM2 outputs (max 32768x512)
__device__ float g_bufC[67108864];               // concat buffers (fp32)
__device__ __nv_bfloat16 g_whi[4194304];         // weight hi planes (all 8 GEMMs)
__device__ __nv_bfloat16 g_wlo[4194304];         // weight lo planes
__device__ float g_sum[1024];
__device__ float g_sumsq[1024];
__device__ float g_scale[1024];
__device__ float g_shift[1024];

// ---------------- PTX helpers ----------------
__device__ __forceinline__ uint32_t smem_u32(const void* p) {
    uint32_t a;
    asm("{ .reg .u64 t; cvta.to.shared.u64 t, %1; cvt.u32.u64 %0, t; }" : "=r"(a) : "l"(p));
    return a;
}
__device__ __forceinline__ void cp16(uint32_t sdst, const void* gsrc) {
    asm volatile("cp.async.cg.shared.global [%0], [%1], 16;" :: "r"(sdst), "l"(gsrc));
}
#define CP_COMMIT() asm volatile("cp.async.commit_group;" ::: "memory")
#define CP_WAIT0()  asm volatile("cp.async.wait_group 0;" ::: "memory")

// named barriers: 256 threads each. FULL ids 1..3, EMPTY ids 4..6
#define BAR_SYNC(id)   asm volatile("bar.sync %0, 256;"   :: "r"(id) : "memory")
#define BAR_ARRIVE(id) asm volatile("bar.arrive %0, 256;" :: "r"(id) : "memory")

__device__ __forceinline__ void ldsm_x4(uint32_t* r, uint32_t addr) {
    asm volatile("ldmatrix.sync.aligned.m8n8.x4.shared.b16 {%0,%1,%2,%3}, [%4];"
                 : "=r"(r[0]), "=r"(r[1]), "=r"(r[2]), "=r"(r[3]) : "r"(addr));
}
__device__ __forceinline__ void ldsm_x4_t(uint32_t* r, uint32_t addr) {
    asm volatile("ldmatrix.sync.aligned.m8n8.x4.trans.shared.b16 {%0,%1,%2,%3}, [%4];"
                 : "=r"(r[0]), "=r"(r[1]), "=r"(r[2]), "=r"(r[3]) : "r"(addr));
}
__device__ __forceinline__ void mma16816(float* d, const uint32_t* a, uint32_t b0, uint32_t b1) {
    asm volatile("mma.sync.aligned.m16n8k16.row.col.f32.bf16.bf16.f32 "
                 "{%0,%1,%2,%3}, {%4,%5,%6,%7}, {%8,%9}, {%0,%1,%2,%3};"
                 : "+f"(d[0]), "+f"(d[1]), "+f"(d[2]), "+f"(d[3])
                 : "r"(a[0]), "r"(a[1]), "r"(a[2]), "r"(a[3]), "r"(b0), "r"(b1));
}

// fp32x4 -> hi/lo bf16x4 (8B each)
__device__ __forceinline__ void split4s(float4 v, char* hp, char* lp) {
    __nv_bfloat162 h01 = __floats2bfloat162_rn(v.x, v.y);
    __nv_bfloat162 h23 = __floats2bfloat162_rn(v.z, v.w);
    float2 f01 = __bfloat1622float2(h01);
    float2 f23 = __bfloat1622float2(h23);
    __nv_bfloat162 l01 = __floats2bfloat162_rn(v.x - f01.x, v.y - f01.y);
    __nv_bfloat162 l23 = __floats2bfloat162_rn(v.z - f23.x, v.w - f23.y);
    uint2 hv, lv;
    hv.x = *reinterpret_cast<uint32_t*>(&h01);
    hv.y = *reinterpret_cast<uint32_t*>(&h23);
    lv.x = *reinterpret_cast<uint32_t*>(&l01);
    lv.y = *reinterpret_cast<uint32_t*>(&l23);
    *reinterpret_cast<uint2*>(hp) = hv;
    *reinterpret_cast<uint2*>(lp) = lv;
}

// ---------------- elementwise kernels ----------------
__global__ void zero_stats_kernel(int n) {
    int i = blockIdx.x * blockDim.x + threadIdx.x;
    if (i < n) { g_sum[i] = 0.f; g_sumsq[i] = 0.f; }
}

__global__ void finalize_stats_kernel(const float* __restrict__ gamma,
                                      const float* __restrict__ beta,
                                      int N, float invM) {
    int i = blockIdx.x * blockDim.x + threadIdx.x;
    if (i >= N) return;
    float mu  = g_sum[i] * invM;
    float var = g_sumsq[i] * invM - mu * mu;
    float sc  = gamma[i] * rsqrtf(var + EPS);
    g_scale[i] = sc;
    g_shift[i] = beta[i] - mu * sc;
}

// W (K,N) fp32 -> bf16 hi/lo planes, same layout
__global__ void wsplit_kernel(const float* __restrict__ W,
                              __nv_bfloat16* __restrict__ hi, __nv_bfloat16* __restrict__ lo,
                              long long total4) {
    for (long long i = (long long)blockIdx.x * blockDim.x + threadIdx.x;
         i < total4; i += (long long)gridDim.x * blockDim.x) {
        float4 v = *(const float4*)(W + i * 4);
        split4s(v, (char*)(hi + i * 4), (char*)(lo + i * 4));
    }
}

__global__ void build_cat_kernel(const float* __restrict__ left,
                                 const float* __restrict__ right,
                                 const int* __restrict__ idx,
                                 float* __restrict__ out,
                                 int rows, int Cl, int Cr,
                                 int outRowsPerBatch, int srcRowsPerBatch) {
    int cols = Cl + Cr;
    int c4n = cols >> 2;
    long long t = (long long)blockIdx.x * blockDim.x + threadIdx.x;
    long long total = (long long)rows * c4n;
    if (t >= total) return;
    int row = (int)(t / c4n);
    int c4 = (int)(t % c4n) * 4;
    float4 v;
    if (c4 < Cl) {
        v = *(const float4*)(left + (size_t)row * Cl + c4);
    } else {
        int b = row / outRowsPerBatch;
        int src = b * srcRowsPerBatch + idx[row];
        v = *(const float4*)(right + (size_t)src * Cr + (c4 - Cl));
    }
    *(float4*)(out + (size_t)row * cols + c4) = v;
}

// ---------------- warp-specialized HMMA GEMM ----------------
// C = f(A) @ W + bias.  A (M,K) fp32; W pre-split bf16 planes (K,N).
// BM=128, BN=128, BK=32; 8 warps: 0-3 consumers (64x64 tiles, ldsm+MMA only),
// 4-7 producers (A LDG+norm+split+STS, W cp.async). 3-stage ring, named barriers.
template <bool NORM, bool STATS>
__global__ __launch_bounds__(256, 1)
void hmma_gemm_kernel(const float* __restrict__ A,
                      const __nv_bfloat16* __restrict__ Wh, const __nv_bfloat16* __restrict__ Wl,
                      const float* __restrict__ bias, float* __restrict__ C,
                      int M, int N, int K) {
    constexpr int A_STR = 80;                 // bytes per A smem row (32 bf16 + pad)
    constexpr int W_STR = 272;                // bytes per W smem row (128 bf16 + pad)
    constexpr int A_PLANE = 128 * A_STR;      // 10240
    constexpr int W_PLANE = 32 * W_STR;       // 8704
    constexpr int OFF_AH = 0;
    constexpr int OFF_AL = A_PLANE;
    constexpr int OFF_WH = 2 * A_PLANE;
    constexpr int OFF_WL = 2 * A_PLANE + W_PLANE;
    constexpr int STAGE = 2 * A_PLANE + 2 * W_PLANE;  // 37888
    constexpr int NSTAGE = 3;

    extern __shared__ char sm[];
    const uint32_t smb = smem_u32(sm);

    const int tid = threadIdx.x;
    const int wid = tid >> 5;
    const int lane = tid & 31;
    const int bm0 = blockIdx.y * 128;
    const int bn0 = blockIdx.x * 128;
    const int T = K >> 5;

    if (wid < 4) {
        // ================= CONSUMER =================
        const int warp_m = (wid >> 1) * 64;
        const int warp_n = (wid & 1) * 64;

        uint32_t a_off[4], b_off[4];
#pragma unroll
        for (int mt = 0; mt < 4; mt++)
            a_off[mt] = (uint32_t)((warp_m + mt * 16 + (lane & 15)) * A_STR + ((lane >> 4) << 3) * 2);
#pragma unroll
        for (int np = 0; np < 4; np++)
            b_off[np] = (uint32_t)((lane & 15) * W_STR + (warp_n + np * 16 + ((lane >> 4) << 3)) * 2);

        float acc[4][8][4];
#pragma unroll
        for (int mt = 0; mt < 4; mt++)
#pragma unroll
            for (int nt = 0; nt < 8; nt++)
#pragma unroll
                for (int q = 0; q < 4; q++) acc[mt][nt][q] = 0.f;

        int s = 0;
        for (int t = 0; t < T; t++) {
            BAR_SYNC(1 + s);
            const uint32_t sbase = smb + s * STAGE;
#pragma unroll
            for (int ks = 0; ks < 2; ks++) {
                uint32_t ah[4][4], al[4][4];
#pragma unroll
                for (int mt = 0; mt < 4; mt++)
                    ldsm_x4(ah[mt], sbase + OFF_AH + a_off[mt] + ks * 32);
#pragma unroll
                for (int mt = 0; mt < 4; mt++)
                    ldsm_x4(al[mt], sbase + OFF_AL + a_off[mt] + ks * 32);
#pragma unroll
                for (int np = 0; np < 4; np++) {
                    uint32_t bh[4], bl[4];
                    ldsm_x4_t(bh, sbase + OFF_WH + b_off[np] + ks * (16 * W_STR));
                    ldsm_x4_t(bl, sbase + OFF_WL + b_off[np] + ks * (16 * W_STR));
                    // product-major: same-acc reuse distance = 8 MMAs
#pragma unroll
                    for (int mt = 0; mt < 4; mt++)
#pragma unroll
                        for (int half = 0; half < 2; half++)
                            mma16816(acc[mt][np * 2 + half], ah[mt], bh[half * 2], bh[half * 2 + 1]);
#pragma unroll
                    for (int mt = 0; mt < 4; mt++)
#pragma unroll
                        for (int half = 0; half < 2; half++)
                            mma16816(acc[mt][np * 2 + half], ah[mt], bl[half * 2], bl[half * 2 + 1]);
#pragma unroll
                    for (int mt = 0; mt < 4; mt++)
#pragma unroll
                        for (int half = 0; half < 2; half++)
                            mma16816(acc[mt][np * 2 + half], al[mt], bh[half * 2], bh[half * 2 + 1]);
                }
            }
            BAR_ARRIVE(4 + s);
            s = (s + 1 == NSTAGE) ? 0 : s + 1;
        }

        // ---- epilogue: bias + store (+ column stats) ----
#pragma unroll
        for (int nt = 0; nt < 8; nt++) {
            int c0 = bn0 + warp_n + (nt >> 1) * 16 + (nt & 1) * 8 + (lane & 3) * 2;
            float b0 = bias[c0], b1 = bias[c0 + 1];
            float s0 = 0.f, s1 = 0.f, q0 = 0.f, q1 = 0.f;
#pragma unroll
            for (int mt = 0; mt < 4; mt++) {
                int r0 = bm0 + warp_m + mt * 16 + (lane >> 2);
                float v0 = acc[mt][nt][0] + b0, v1 = acc[mt][nt][1] + b1;
                float v2 = acc[mt][nt][2] + b0, v3 = acc[mt][nt][3] + b1;
                float2 p0; p0.x = v0; p0.y = v1;
                float2 p1; p1.x = v2; p1.y = v3;
                *(float2*)(C + (size_t)r0 * N + c0) = p0;
                *(float2*)(C + (size_t)(r0 + 8) * N + c0) = p1;
                if (STATS) {
                    s0 += v0 + v2; s1 += v1 + v3;
                    q0 += v0 * v0 + v2 * v2; q1 += v1 * v1 + v3 * v3;
                }
            }
            if (STATS) {
#pragma unroll
                for (int off = 4; off < 32; off <<= 1) {
                    s0 += __shfl_xor_sync(0xFFFFFFFFu, s0, off);
                    s1 += __shfl_xor_sync(0xFFFFFFFFu, s1, off);
                    q0 += __shfl_xor_sync(0xFFFFFFFFu, q0, off);
                    q1 += __shfl_xor_sync(0xFFFFFFFFu, q1, off);
                }
                if ((lane >> 2) == 0) {
                    atomicAdd(&g_sum[c0], s0);
                    atomicAdd(&g_sum[c0 + 1], s1);
                    atomicAdd(&g_sumsq[c0], q0);
                    atomicAdd(&g_sumsq[c0 + 1], q1);
                }
            }
        }
    } else {
        // ================= PRODUCER =================
        const int ptid = tid - 128;   // 0..127

        // A mapping: 1024 float4, 8 per producer thread
        int a_row[8], a_c[8];
        uint32_t a_soff[8];
#pragma unroll
        for (int i = 0; i < 8; i++) {
            int idx = ptid + (i << 7);
            a_row[i] = idx >> 3;
            a_c[i] = (idx & 7) << 2;
            a_soff[i] = a_row[i] * A_STR + a_c[i] * 2;
        }
        // W mapping: 512 chunks(16B)/plane, 4 per producer thread
        int wRow[4], wCol[4];
        uint32_t wS[4];
#pragma unroll
        for (int i = 0; i < 4; i++) {
            int c = ptid + (i << 7);
            wRow[i] = c >> 4;
            wCol[i] = (c & 15) * 8;
            wS[i] = wRow[i] * W_STR + (c & 15) * 16;
        }

        int s = 0;
        for (int t = 0; t < T; t++) {
            if (t >= NSTAGE) BAR_SYNC(4 + s);
            const int k0 = t << 5;
            const uint32_t nb = smb + s * STAGE;
            char* nbc = sm + s * STAGE;
#pragma unroll
            for (int i = 0; i < 4; i++) {
                size_t gw = (size_t)(k0 + wRow[i]) * N + bn0 + wCol[i];
                cp16(nb + OFF_WH + wS[i], Wh + gw);
                cp16(nb + OFF_WL + wS[i], Wl + gw);
            }
            CP_COMMIT();
            float4 ar[8];
#pragma unroll
            for (int i = 0; i < 8; i++)
                ar[i] = *(const float4*)(A + (size_t)(bm0 + a_row[i]) * K + k0 + a_c[i]);
#pragma unroll
            for (int i = 0; i < 8; i++) {
                float4 v = ar[i];
                if (NORM) {
                    float4 sc = *(const float4*)(g_scale + k0 + a_c[i]);
                    float4 sh = *(const float4*)(g_shift + k0 + a_c[i]);
                    v.x = fmaxf(v.x * sc.x + sh.x, 0.f);
                    v.y = fmaxf(v.y * sc.y + sh.y, 0.f);
                    v.z = fmaxf(v.z * sc.z + sh.z, 0.f);
                    v.w = fmaxf(v.w * sc.w + sh.w, 0.f);
                }
                split4s(v, nbc + OFF_AH + a_soff[i], nbc + OFF_AL + a_soff[i]);
            }
            CP_WAIT0();
            BAR_ARRIVE(1 + s);
            s = (s + 1 == NSTAGE) ? 0 : s + 1;
        }
    }
}

// ---------------- host orchestration ----------------
static const int GEMM_SMEM = 3 * 37888;   // 113664

static __nv_bfloat16 *s_whi, *s_wlo;
static float *s_bufA, *s_bufB, *s_bufC;

template <bool NORM, bool STATS>
static void run_gemm(const float* A, size_t woff, const float* bias, float* C,
                     int M, int N, int K) {
    dim3 grid(N / 128, M / 128);
    hmma_gemm_kernel<NORM, STATS><<<grid, 256, GEMM_SMEM>>>(A, s_whi + woff, s_wlo + woff,
                                                            bias, C, M, N, K);
}

extern "C" void kernel_launch(void* const* d_in, const int* in_sizes, int n_in,
                              void* d_out, int out_size) {
    const float* f0 = (const float*)d_in[0];
    const float* f1 = (const float*)d_in[1];
    const float* f2 = (const float*)d_in[2];
    const float* up0_w1 = (const float*)d_in[3];
    const float* up0_b1 = (const float*)d_in[4];
    const float* up0_g  = (const float*)d_in[5];
    const float* up0_be = (const float*)d_in[6];
    const float* up0_w2 = (const float*)d_in[7];
    const float* up0_b2 = (const float*)d_in[8];
    const float* up1_w1 = (const float*)d_in[9];
    const float* up1_b1 = (const float*)d_in[10];
    const float* up1_g  = (const float*)d_in[11];
    const float* up1_be = (const float*)d_in[12];
    const float* up1_w2 = (const float*)d_in[13];
    const float* up1_b2 = (const float*)d_in[14];
    const float* skip0_w1 = (const float*)d_in[15];
    const float* skip0_b1 = (const float*)d_in[16];
    const float* skip0_g  = (const float*)d_in[17];
    const float* skip0_be = (const float*)d_in[18];
    const float* skip0_w2 = (const float*)d_in[19];
    const float* skip0_b2 = (const float*)d_in[20];
    const float* skip1_w1 = (const float*)d_in[21];
    const float* skip1_b1 = (const float*)d_in[22];
    const float* skip1_g  = (const float*)d_in[23];
    const float* skip1_be = (const float*)d_in[24];
    const float* skip1_w2 = (const float*)d_in[25];
    const float* skip1_b2 = (const float*)d_in[26];
    const int*   pool0 = (const int*)d_in[27];
    const int*   pool1 = (const int*)d_in[28];
    float* out = (float*)d_out;

    cudaGetSymbolAddress((void**)&s_bufA, g_bufA);
    cudaGetSymbolAddress((void**)&s_bufB, g_bufB);
    cudaGetSymbolAddress((void**)&s_bufC, g_bufC);
    cudaGetSymbolAddress((void**)&s_whi, g_whi);
    cudaGetSymbolAddress((void**)&s_wlo, g_wlo);

    cudaFuncSetAttribute(hmma_gemm_kernel<false, true>, cudaFuncAttributeMaxDynamicSharedMemorySize, GEMM_SMEM);
    cudaFuncSetAttribute(hmma_gemm_kernel<true, false>, cudaFuncAttributeMaxDynamicSharedMemorySize, GEMM_SMEM);

    const int B = 4;
    const int N0 = 32768, N1 = 8192, N2 = 2048;
    const int C0 = 256, C1 = 512, C2 = 1024;
    const int M_u1 = B * N2, M_s1 = B * N1, M_s0 = B * N0;

    // weight plane offsets (K,N) layout
    const size_t O_U1W1 = 0;
    const size_t O_U1W2 = 1048576;
    const size_t O_S1W1 = 1572864;
    const size_t O_S1W2 = 2621440;
    const size_t O_U0W1 = 3145728;
    const size_t O_U0W2 = 3407872;
    const size_t O_S0W1 = 3538944;
    const size_t O_S0W2 = 3801088;

    // ---- up1 MLP: f2 (8192,1024) -> 1024 -> 512 ----
    zero_stats_kernel<<<4, 256>>>(1024);
    wsplit_kernel<<<512, 256>>>(up1_w1, s_whi + O_U1W1, s_wlo + O_U1W1, (long long)C2 * C2 / 4);
    wsplit_kernel<<<512, 256>>>(up1_w2, s_whi + O_U1W2, s_wlo + O_U1W2, (long long)C2 * C1 / 4);
    run_gemm<false, true>(f2, O_U1W1, up1_b1, s_bufA, M_u1, C2, C2);     // profiled slot
    finalize_stats_kernel<<<4, 256>>>(up1_g, up1_be, C2, 1.0f / M_u1);
    run_gemm<true, false>(s_bufA, O_U1W2, up1_b2, s_bufB, M_u1, C1, C2);

    // ---- gather pool1 + concat f1 -> bufC (32768,1024) ----
    {
        long long total = (long long)M_s1 * ((2 * C1) / 4);
        build_cat_kernel<<<(int)((total + 255) / 256), 256>>>(f1, s_bufB, pool1, s_bufC,
                                                              M_s1, C1, C1, N1, N2);
    }

    // ---- skip1 MLP: (32768,1024) -> 1024 -> 512 ----
    zero_stats_kernel<<<4, 256>>>(1024);
    wsplit_kernel<<<512, 256>>>(skip1_w1, s_whi + O_S1W1, s_wlo + O_S1W1, (long long)(2 * C1) * (2 * C1) / 4);
    wsplit_kernel<<<512, 256>>>(skip1_w2, s_whi + O_S1W2, s_wlo + O_S1W2, (long long)(2 * C1) * C1 / 4);
    run_gemm<false, true>(s_bufC, O_S1W1, skip1_b1, s_bufA, M_s1, 2 * C1, 2 * C1);
    finalize_stats_kernel<<<4, 256>>>(skip1_g, skip1_be, 2 * C1, 1.0f / M_s1);
    run_gemm<true, false>(s_bufA, O_S1W2, skip1_b2, s_bufB, M_s1, C1, 2 * C1);

    // ---- up0 MLP: (32768,512) -> 512 -> 256 ----
    zero_stats_kernel<<<2, 256>>>(512);
    wsplit_kernel<<<256, 256>>>(up0_w1, s_whi + O_U0W1, s_wlo + O_U0W1, (long long)C1 * C1 / 4);
    wsplit_kernel<<<256, 256>>>(up0_w2, s_whi + O_U0W2, s_wlo + O_U0W2, (long long)C1 * C0 / 4);
    run_gemm<false, true>(s_bufB, O_U0W1, up0_b1, s_bufA, M_s1, C1, C1);
    finalize_stats_kernel<<<2, 256>>>(up0_g, up0_be, C1, 1.0f / M_s1);
    run_gemm<true, false>(s_bufA, O_U0W2, up0_b2, s_bufB, M_s1, C0, C1);

    // ---- gather pool0 + concat f0 -> bufC (131072,512) ----
    {
        long long total = (long long)M_s0 * ((2 * C0) / 4);
        build_cat_kernel<<<(int)((total + 255) / 256), 256>>>(f0, s_bufB, pool0, s_bufC,
                                                              M_s0, C0, C0, N0, N1);
    }

    // ---- skip0 MLP: (131072,512) -> 512 -> 256 -> out ----
    zero_stats_kernel<<<2, 256>>>(512);
    wsplit_kernel<<<256, 256>>>(skip0_w1, s_whi + O_S0W1, s_wlo + O_S0W1, (long long)(2 * C0) * (2 * C0) / 4);
    wsplit_kernel<<<256, 256>>>(skip0_w2, s_whi + O_S0W2, s_wlo + O_S0W2, (long long)(2 * C0) * C0 / 4);
    run_gemm<false, true>(s_bufC, O_S0W1, skip0_b1, s_bufA, M_s0, 2 * C0, 2 * C0);
    finalize_stats_kernel<<<2, 256>>>(skip0_g, skip0_be, 2 * C0, 1.0f / M_s0);
    run_gemm<true, false>(s_bufA, O_S0W2, skip0_b2, out, M_s0, C0, 2 * C0);
}

// round 10
// speedup vs baseline: 1.4664x; 1.4410x over previous
#include <cuda_runtime.h>
#include <cuda_fp16.h>
#include <cstdint>
#include <math.h>

#define EPS 1e-5f

// ---------------- scratch (device globals) ----------------
__device__ float g_bufA[67108864];               // GEMM1 H outputs (max 131072x512)
__device__ float g_bufB[16777216];               // GEMM2 outputs (max 32768x512)
__device__ float g_bufC[67108864];               // concat buffers (fp32)
__device__ __half g_whi[4194304];                // weight hi planes (fp16, all 8 GEMMs)
__device__ __half g_wlo[4194304];                // weight lo planes (fp16)
__device__ float g_sum[1024];
__device__ float g_sumsq[1024];
__device__ float g_scale[1024];
__device__ float g_shift[1024];

// ---------------- PTX helpers ----------------
__device__ __forceinline__ uint32_t smem_u32(const void* p) {
    uint32_t a;
    asm("{ .reg .u64 t; cvta.to.shared.u64 t, %1; cvt.u32.u64 %0, t; }" : "=r"(a) : "l"(p));
    return a;
}
__device__ __forceinline__ void cp16(uint32_t sdst, const void* gsrc) {
    asm volatile("cp.async.cg.shared.global [%0], [%1], 16;" :: "r"(sdst), "l"(gsrc));
}
#define CP_COMMIT() asm volatile("cp.async.commit_group;" ::: "memory")
#define CP_WAIT0()  asm volatile("cp.async.wait_group 0;" ::: "memory")

__device__ __forceinline__ void ldsm_x4(uint32_t* r, uint32_t addr) {
    asm volatile("ldmatrix.sync.aligned.m8n8.x4.shared.b16 {%0,%1,%2,%3}, [%4];"
                 : "=r"(r[0]), "=r"(r[1]), "=r"(r[2]), "=r"(r[3]) : "r"(addr));
}
__device__ __forceinline__ void ldsm_x4_t(uint32_t* r, uint32_t addr) {
    asm volatile("ldmatrix.sync.aligned.m8n8.x4.trans.shared.b16 {%0,%1,%2,%3}, [%4];"
                 : "=r"(r[0]), "=r"(r[1]), "=r"(r[2]), "=r"(r[3]) : "r"(addr));
}
__device__ __forceinline__ void mma16816(float* d, const uint32_t* a, uint32_t b0, uint32_t b1) {
    asm volatile("mma.sync.aligned.m16n8k16.row.col.f32.f16.f16.f32 "
                 "{%0,%1,%2,%3}, {%4,%5,%6,%7}, {%8,%9}, {%0,%1,%2,%3};"
                 : "+f"(d[0]), "+f"(d[1]), "+f"(d[2]), "+f"(d[3])
                 : "r"(a[0]), "r"(a[1]), "r"(a[2]), "r"(a[3]), "r"(b0), "r"(b1));
}

// fp32x4 -> fp16x4 (8B)
__device__ __forceinline__ void cvt4h(float4 v, char* p) {
    __half2 h01 = __floats2half2_rn(v.x, v.y);
    __half2 h23 = __floats2half2_rn(v.z, v.w);
    uint2 u;
    u.x = *reinterpret_cast<uint32_t*>(&h01);
    u.y = *reinterpret_cast<uint32_t*>(&h23);
    *reinterpret_cast<uint2*>(p) = u;
}

// fp32x4 -> fp16 hi/lo planes (8B each)
__device__ __forceinline__ void split4h(float4 v, char* hp, char* lp) {
    __half2 h01 = __floats2half2_rn(v.x, v.y);
    __half2 h23 = __floats2half2_rn(v.z, v.w);
    float2 f01 = __half22float2(h01);
    float2 f23 = __half22float2(h23);
    __half2 l01 = __floats2half2_rn(v.x - f01.x, v.y - f01.y);
    __half2 l23 = __floats2half2_rn(v.z - f23.x, v.w - f23.y);
    uint2 hv, lv;
    hv.x = *reinterpret_cast<uint32_t*>(&h01);
    hv.y = *reinterpret_cast<uint32_t*>(&h23);
    lv.x = *reinterpret_cast<uint32_t*>(&l01);
    lv.y = *reinterpret_cast<uint32_t*>(&l23);
    *reinterpret_cast<uint2*>(hp) = hv;
    *reinterpret_cast<uint2*>(lp) = lv;
}

// ---------------- elementwise kernels ----------------
__global__ void zero_stats_kernel(int n) {
    int i = blockIdx.x * blockDim.x + threadIdx.x;
    if (i < n) { g_sum[i] = 0.f; g_sumsq[i] = 0.f; }
}

__global__ void finalize_stats_kernel(const float* __restrict__ gamma,
                                      const float* __restrict__ beta,
                                      int N, float invM) {
    int i = blockIdx.x * blockDim.x + threadIdx.x;
    if (i >= N) return;
    float mu  = g_sum[i] * invM;
    float var = g_sumsq[i] * invM - mu * mu;
    float sc  = gamma[i] * rsqrtf(var + EPS);
    g_scale[i] = sc;
    g_shift[i] = beta[i] - mu * sc;
}

// W (K,N) fp32 -> fp16 hi/lo planes, same layout
__global__ void wsplit_kernel(const float* __restrict__ W,
                              __half* __restrict__ hi, __half* __restrict__ lo,
                              long long total4) {
    for (long long i = (long long)blockIdx.x * blockDim.x + threadIdx.x;
         i < total4; i += (long long)gridDim.x * blockDim.x) {
        float4 v = *(const float4*)(W + i * 4);
        split4h(v, (char*)(hi + i * 4), (char*)(lo + i * 4));
    }
}

__global__ void build_cat_kernel(const float* __restrict__ left,
                                 const float* __restrict__ right,
                                 const int* __restrict__ idx,
                                 float* __restrict__ out,
                                 int rows, int Cl, int Cr,
                                 int outRowsPerBatch, int srcRowsPerBatch) {
    int cols = Cl + Cr;
    int c4n = cols >> 2;
    long long t = (long long)blockIdx.x * blockDim.x + threadIdx.x;
    long long total = (long long)rows * c4n;
    if (t >= total) return;
    int row = (int)(t / c4n);
    int c4 = (int)(t % c4n) * 4;
    float4 v;
    if (c4 < Cl) {
        v = *(const float4*)(left + (size_t)row * Cl + c4);
    } else {
        int b = row / outRowsPerBatch;
        int src = b * srcRowsPerBatch + idx[row];
        v = *(const float4*)(right + (size_t)src * Cr + (c4 - Cl));
    }
    *(float4*)(out + (size_t)row * cols + c4) = v;
}

// ---------------- HMMA GEMM (fp16 2-product) ----------------
// C = f(A) @ W + bias.  A (M,K) fp32 -> fp16 in-kernel; W pre-split fp16 hi/lo (K,N).
// BM=128, BN=128, BK=32; 256 threads (8 warps, 2x4), warp tile 64x32.
// 2 products: a*wh + a*wl.
template <bool NORM, bool STATS>
__global__ __launch_bounds__(256, 2)
void hmma_gemm_kernel(const float* __restrict__ A,
                      const __half* __restrict__ Wh, const __half* __restrict__ Wl,
                      const float* __restrict__ bias, float* __restrict__ C,
                      int M, int N, int K) {
    constexpr int A_STR = 80;                 // bytes per A smem row (32 fp16 + pad)
    constexpr int W_STR = 272;                // bytes per W smem row (128 fp16 + pad)
    constexpr int A_PLANE = 128 * A_STR;      // 10240
    constexpr int W_PLANE = 32 * W_STR;       // 8704
    constexpr int OFF_A  = 0;
    constexpr int OFF_WH = A_PLANE;
    constexpr int OFF_WL = A_PLANE + W_PLANE;
    constexpr int STAGE = A_PLANE + 2 * W_PLANE;   // 27648

    extern __shared__ char sm[];
    const uint32_t smb = smem_u32(sm);

    const int tid = threadIdx.x;
    const int wid = tid >> 5;
    const int lane = tid & 31;
    const int warp_m = (wid >> 2) * 64;
    const int warp_n = (wid & 3) * 32;
    const int bm0 = blockIdx.y * 128;
    const int bn0 = blockIdx.x * 128;
    const int T = K >> 5;

    // A fp32 LDG mapping: 128x32 = 1024 float4, 4 per thread
    int a_row[4], a_c[4];
    uint32_t a_soff[4];
#pragma unroll
    for (int i = 0; i < 4; i++) {
        int idx = tid + (i << 8);
        a_row[i] = idx >> 3;
        a_c[i] = (idx & 7) << 2;
        a_soff[i] = a_row[i] * A_STR + a_c[i] * 2;
    }
    // W cp.async mapping: per plane 512 x 16B chunks, 2 per thread
    int wRow[2], wCol[2];
    uint32_t wS[2];
#pragma unroll
    for (int i = 0; i < 2; i++) {
        int c = tid + (i << 8);
        wRow[i] = c >> 4;
        wCol[i] = (c & 15) * 8;
        wS[i] = wRow[i] * W_STR + (c & 15) * 16;
    }

    // ldmatrix offsets (stage-relative)
    uint32_t a_off[4], b_off[2];
#pragma unroll
    for (int mt = 0; mt < 4; mt++)
        a_off[mt] = (uint32_t)((warp_m + mt * 16 + (lane & 15)) * A_STR + ((lane >> 4) << 3) * 2);
#pragma unroll
    for (int np = 0; np < 2; np++)
        b_off[np] = (uint32_t)((lane & 15) * W_STR + (warp_n + np * 16 + ((lane >> 4) << 3)) * 2);

    float acc[4][4][4];
#pragma unroll
    for (int mt = 0; mt < 4; mt++)
#pragma unroll
        for (int nt = 0; nt < 4; nt++)
#pragma unroll
            for (int q = 0; q < 4; q++) acc[mt][nt][q] = 0.f;

    float4 ar[4];

    // ---- prologue: W cp stage0, A ldg+convert stage0 ----
    {
#pragma unroll
        for (int i = 0; i < 2; i++) {
            size_t gw = (size_t)wRow[i] * N + bn0 + wCol[i];
            cp16(smb + OFF_WH + wS[i], Wh + gw);
            cp16(smb + OFF_WL + wS[i], Wl + gw);
        }
        CP_COMMIT();
#pragma unroll
        for (int i = 0; i < 4; i++)
            ar[i] = *(const float4*)(A + (size_t)(bm0 + a_row[i]) * K + a_c[i]);
#pragma unroll
        for (int i = 0; i < 4; i++) {
            float4 v = ar[i];
            if (NORM) {
                float4 sc = *(const float4*)(g_scale + a_c[i]);
                float4 sh = *(const float4*)(g_shift + a_c[i]);
                v.x = fmaxf(v.x * sc.x + sh.x, 0.f);
                v.y = fmaxf(v.y * sc.y + sh.y, 0.f);
                v.z = fmaxf(v.z * sc.z + sh.z, 0.f);
                v.w = fmaxf(v.w * sc.w + sh.w, 0.f);
            }
            cvt4h(v, sm + OFF_A + a_soff[i]);
        }
        CP_WAIT0();
    }
    __syncthreads();

    for (int t = 0; t < T; t++) {
        const int s = t & 1;
        const uint32_t sbase = smb + s * STAGE;
        const bool has_next = (t + 1 < T);
        const int k0n = (t + 1) << 5;

        if (has_next) {
            uint32_t nb = smb + (s ^ 1) * STAGE;
#pragma unroll
            for (int i = 0; i < 2; i++) {
                size_t gw = (size_t)(k0n + wRow[i]) * N + bn0 + wCol[i];
                cp16(nb + OFF_WH + wS[i], Wh + gw);
                cp16(nb + OFF_WL + wS[i], Wl + gw);
            }
            CP_COMMIT();
#pragma unroll
            for (int i = 0; i < 4; i++)
                ar[i] = *(const float4*)(A + (size_t)(bm0 + a_row[i]) * K + k0n + a_c[i]);
        }

#pragma unroll
        for (int ks = 0; ks < 2; ks++) {
            uint32_t ah[4][4];
#pragma unroll
            for (int mt = 0; mt < 4; mt++)
                ldsm_x4(ah[mt], sbase + OFF_A + a_off[mt] + ks * 32);
#pragma unroll
            for (int np = 0; np < 2; np++) {
                uint32_t bh[4], bl[4];
                ldsm_x4_t(bh, sbase + OFF_WH + b_off[np] + ks * (16 * W_STR));
                ldsm_x4_t(bl, sbase + OFF_WL + b_off[np] + ks * (16 * W_STR));
                // product-major: same-acc reuse distance = 8 MMAs
#pragma unroll
                for (int mt = 0; mt < 4; mt++)
#pragma unroll
                    for (int half = 0; half < 2; half++)
                        mma16816(acc[mt][np * 2 + half], ah[mt], bh[half * 2], bh[half * 2 + 1]);
#pragma unroll
                for (int mt = 0; mt < 4; mt++)
#pragma unroll
                    for (int half = 0; half < 2; half++)
                        mma16816(acc[mt][np * 2 + half], ah[mt], bl[half * 2], bl[half * 2 + 1]);
            }
        }

        if (has_next) {
            char* nb = sm + (s ^ 1) * STAGE;
#pragma unroll
            for (int i = 0; i < 4; i++) {
                float4 v = ar[i];
                if (NORM) {
                    float4 sc = *(const float4*)(g_scale + k0n + a_c[i]);
                    float4 sh = *(const float4*)(g_shift + k0n + a_c[i]);
                    v.x = fmaxf(v.x * sc.x + sh.x, 0.f);
                    v.y = fmaxf(v.y * sc.y + sh.y, 0.f);
                    v.z = fmaxf(v.z * sc.z + sh.z, 0.f);
                    v.w = fmaxf(v.w * sc.w + sh.w, 0.f);
                }
                cvt4h(v, nb + OFF_A + a_soff[i]);
            }
            CP_WAIT0();
        }
        __syncthreads();
    }

    // ---- epilogue: bias + store (+ column stats) ----
    // nt -> col: c0 = bn0 + warp_n + (nt>>1)*16 + (nt&1)*8 + (lane&3)*2
#pragma unroll
    for (int nt = 0; nt < 4; nt++) {
        int c0 = bn0 + warp_n + (nt >> 1) * 16 + (nt & 1) * 8 + (lane & 3) * 2;
        float b0 = bias[c0], b1 = bias[c0 + 1];
        float s0 = 0.f, s1 = 0.f, q0 = 0.f, q1 = 0.f;
#pragma unroll
        for (int mt = 0; mt < 4; mt++) {
            int r0 = bm0 + warp_m + mt * 16 + (lane >> 2);
            float v0 = acc[mt][nt][0] + b0, v1 = acc[mt][nt][1] + b1;
            float v2 = acc[mt][nt][2] + b0, v3 = acc[mt][nt][3] + b1;
            float2 p0; p0.x = v0; p0.y = v1;
            float2 p1; p1.x = v2; p1.y = v3;
            *(float2*)(C + (size_t)r0 * N + c0) = p0;
            *(float2*)(C + (size_t)(r0 + 8) * N + c0) = p1;
            if (STATS) {
                s0 += v0 + v2; s1 += v1 + v3;
                q0 += v0 * v0 + v2 * v2; q1 += v1 * v1 + v3 * v3;
            }
        }
        if (STATS) {
#pragma unroll
            for (int off = 4; off < 32; off <<= 1) {
                s0 += __shfl_xor_sync(0xFFFFFFFFu, s0, off);
                s1 += __shfl_xor_sync(0xFFFFFFFFu, s1, off);
                q0 += __shfl_xor_sync(0xFFFFFFFFu, q0, off);
                q1 += __shfl_xor_sync(0xFFFFFFFFu, q1, off);
            }
            if ((lane >> 2) == 0) {
                atomicAdd(&g_sum[c0], s0);
                atomicAdd(&g_sum[c0 + 1], s1);
                atomicAdd(&g_sumsq[c0], q0);
                atomicAdd(&g_sumsq[c0 + 1], q1);
            }
        }
    }
}

// ---------------- host orchestration ----------------
static const int GEMM_SMEM = 2 * 27648;   // 55296

static __half *s_whi, *s_wlo;
static float *s_bufA, *s_bufB, *s_bufC;

template <bool NORM, bool STATS>
static void run_gemm(const float* A, size_t woff, const float* bias, float* C,
                     int M, int N, int K) {
    dim3 grid(N / 128, M / 128);
    hmma_gemm_kernel<NORM, STATS><<<grid, 256, GEMM_SMEM>>>(A, s_whi + woff, s_wlo + woff,
                                                            bias, C, M, N, K);
}

extern "C" void kernel_launch(void* const* d_in, const int* in_sizes, int n_in,
                              void* d_out, int out_size) {
    const float* f0 = (const float*)d_in[0];
    const float* f1 = (const float*)d_in[1];
    const float* f2 = (const float*)d_in[2];
    const float* up0_w1 = (const float*)d_in[3];
    const float* up0_b1 = (const float*)d_in[4];
    const float* up0_g  = (const float*)d_in[5];
    const float* up0_be = (const float*)d_in[6];
    const float* up0_w2 = (const float*)d_in[7];
    const float* up0_b2 = (const float*)d_in[8];
    const float* up1_w1 = (const float*)d_in[9];
    const float* up1_b1 = (const float*)d_in[10];
    const float* up1_g  = (const float*)d_in[11];
    const float* up1_be = (const float*)d_in[12];
    const float* up1_w2 = (const float*)d_in[13];
    const float* up1_b2 = (const float*)d_in[14];
    const float* skip0_w1 = (const float*)d_in[15];
    const float* skip0_b1 = (const float*)d_in[16];
    const float* skip0_g  = (const float*)d_in[17];
    const float* skip0_be = (const float*)d_in[18];
    const float* skip0_w2 = (const float*)d_in[19];
    const float* skip0_b2 = (const float*)d_in[20];
    const float* skip1_w1 = (const float*)d_in[21];
    const float* skip1_b1 = (const float*)d_in[22];
    const float* skip1_g  = (const float*)d_in[23];
    const float* skip1_be = (const float*)d_in[24];
    const float* skip1_w2 = (const float*)d_in[25];
    const float* skip1_b2 = (const float*)d_in[26];
    const int*   pool0 = (const int*)d_in[27];
    const int*   pool1 = (const int*)d_in[28];
    float* out = (float*)d_out;

    cudaGetSymbolAddress((void**)&s_bufA, g_bufA);
    cudaGetSymbolAddress((void**)&s_bufB, g_bufB);
    cudaGetSymbolAddress((void**)&s_bufC, g_bufC);
    cudaGetSymbolAddress((void**)&s_whi, g_whi);
    cudaGetSymbolAddress((void**)&s_wlo, g_wlo);

    cudaFuncSetAttribute(hmma_gemm_kernel<false, true>, cudaFuncAttributeMaxDynamicSharedMemorySize, GEMM_SMEM);
    cudaFuncSetAttribute(hmma_gemm_kernel<true, false>, cudaFuncAttributeMaxDynamicSharedMemorySize, GEMM_SMEM);

    const int B = 4;
    const int N0 = 32768, N1 = 8192, N2 = 2048;
    const int C0 = 256, C1 = 512, C2 = 1024;
    const int M_u1 = B * N2, M_s1 = B * N1, M_s0 = B * N0;

    // weight plane offsets (K,N) layout
    const size_t O_U1W1 = 0;
    const size_t O_U1W2 = 1048576;
    const size_t O_S1W1 = 1572864;
    const size_t O_S1W2 = 2621440;
    const size_t O_U0W1 = 3145728;
    const size_t O_U0W2 = 3407872;
    const size_t O_S0W1 = 3538944;
    const size_t O_S0W2 = 3801088;

    // ---- up1 MLP: f2 (8192,1024) -> 1024 -> 512 ----
    zero_stats_kernel<<<4, 256>>>(1024);
    wsplit_kernel<<<512, 256>>>(up1_w1, s_whi + O_U1W1, s_wlo + O_U1W1, (long long)C2 * C2 / 4);
    wsplit_kernel<<<512, 256>>>(up1_w2, s_whi + O_U1W2, s_wlo + O_U1W2, (long long)C2 * C1 / 4);
    run_gemm<false, true>(f2, O_U1W1, up1_b1, s_bufA, M_u1, C2, C2);     // profiled slot
    finalize_stats_kernel<<<4, 256>>>(up1_g, up1_be, C2, 1.0f / M_u1);
    run_gemm<true, false>(s_bufA, O_U1W2, up1_b2, s_bufB, M_u1, C1, C2);

    // ---- gather pool1 + concat f1 -> bufC (32768,1024) ----
    {
        long long total = (long long)M_s1 * ((2 * C1) / 4);
        build_cat_kernel<<<(int)((total + 255) / 256), 256>>>(f1, s_bufB, pool1, s_bufC,
                                                              M_s1, C1, C1, N1, N2);
    }

    // ---- skip1 MLP: (32768,1024) -> 1024 -> 512 ----
    zero_stats_kernel<<<4, 256>>>(1024);
    wsplit_kernel<<<512, 256>>>(skip1_w1, s_whi + O_S1W1, s_wlo + O_S1W1, (long long)(2 * C1) * (2 * C1) / 4);
    wsplit_kernel<<<512, 256>>>(skip1_w2, s_whi + O_S1W2, s_wlo + O_S1W2, (long long)(2 * C1) * C1 / 4);
    run_gemm<false, true>(s_bufC, O_S1W1, skip1_b1, s_bufA, M_s1, 2 * C1, 2 * C1);
    finalize_stats_kernel<<<4, 256>>>(skip1_g, skip1_be, 2 * C1, 1.0f / M_s1);
    run_gemm<true, false>(s_bufA, O_S1W2, skip1_b2, s_bufB, M_s1, C1, 2 * C1);

    // ---- up0 MLP: (32768,512) -> 512 -> 256 ----
    zero_stats_kernel<<<2, 256>>>(512);
    wsplit_kernel<<<256, 256>>>(up0_w1, s_whi + O_U0W1, s_wlo + O_U0W1, (long long)C1 * C1 / 4);
    wsplit_kernel<<<256, 256>>>(up0_w2, s_whi + O_U0W2, s_wlo + O_U0W2, (long long)C1 * C0 / 4);
    run_gemm<false, true>(s_bufB, O_U0W1, up0_b1, s_bufA, M_s1, C1, C1);
    finalize_stats_kernel<<<2, 256>>>(up0_g, up0_be, C1, 1.0f / M_s1);
    run_gemm<true, false>(s_bufA, O_U0W2, up0_b2, s_bufB, M_s1, C0, C1);

    // ---- gather pool0 + concat f0 -> bufC (131072,512) ----
    {
        long long total = (long long)M_s0 * ((2 * C0) / 4);
        build_cat_kernel<<<(int)((total + 255) / 256), 256>>>(f0, s_bufB, pool0, s_bufC,
                                                              M_s0, C0, C0, N0, N1);
    }

    // ---- skip0 MLP: (131072,512) -> 512 -> 256 -> out ----
    zero_stats_kernel<<<2, 256>>>(512);
    wsplit_kernel<<<256, 256>>>(skip0_w1, s_whi + O_S0W1, s_wlo + O_S0W1, (long long)(2 * C0) * (2 * C0) / 4);
    wsplit_kernel<<<256, 256>>>(skip0_w2, s_whi + O_S0W2, s_wlo + O_S0W2, (long long)(2 * C0) * C0 / 4);
    run_gemm<false, true>(s_bufC, O_S0W1, skip0_b1, s_bufA, M_s0, 2 * C0, 2 * C0);
    finalize_stats_kernel<<<2, 256>>>(skip0_g, skip0_be, 2 * C0, 1.0f / M_s0);
    run_gemm<true, false>(s_bufA, O_S0W2, skip0_b2, out, M_s0, C0, 2 * C0);
}

// round 11
// speedup vs baseline: 1.4979x; 1.0214x over previous
#include <cuda_runtime.h>
#include <cuda_fp16.h>
#include <cstdint>
#include <math.h>

#define EPS 1e-5f

// ---------------- scratch (device globals) ----------------
__device__ float g_bufA[67108864];               // GEMM1 H outputs (max 131072x512)
__device__ float g_bufB[16777216];               // GEMM2 outputs (max 32768x512)
__device__ __half g_whi[4194304];                // weight hi planes (fp16, all 8 GEMMs)
__device__ __half g_wlo[4194304];                // weight lo planes (fp16)
__device__ float g_sum[1024];
__device__ float g_sumsq[1024];
__device__ float g_scale[1024];
__device__ float g_shift[1024];

// ---------------- PTX helpers ----------------
__device__ __forceinline__ uint32_t smem_u32(const void* p) {
    uint32_t a;
    asm("{ .reg .u64 t; cvta.to.shared.u64 t, %1; cvt.u32.u64 %0, t; }" : "=r"(a) : "l"(p));
    return a;
}
__device__ __forceinline__ void cp16(uint32_t sdst, const void* gsrc) {
    asm volatile("cp.async.cg.shared.global [%0], [%1], 16;" :: "r"(sdst), "l"(gsrc));
}
#define CP_COMMIT() asm volatile("cp.async.commit_group;" ::: "memory")
#define CP_WAIT0()  asm volatile("cp.async.wait_group 0;" ::: "memory")

__device__ __forceinline__ void ldsm_x4(uint32_t* r, uint32_t addr) {
    asm volatile("ldmatrix.sync.aligned.m8n8.x4.shared.b16 {%0,%1,%2,%3}, [%4];"
                 : "=r"(r[0]), "=r"(r[1]), "=r"(r[2]), "=r"(r[3]) : "r"(addr));
}
__device__ __forceinline__ void ldsm_x4_t(uint32_t* r, uint32_t addr) {
    asm volatile("ldmatrix.sync.aligned.m8n8.x4.trans.shared.b16 {%0,%1,%2,%3}, [%4];"
                 : "=r"(r[0]), "=r"(r[1]), "=r"(r[2]), "=r"(r[3]) : "r"(addr));
}
__device__ __forceinline__ void mma16816(float* d, const uint32_t* a, uint32_t b0, uint32_t b1) {
    asm volatile("mma.sync.aligned.m16n8k16.row.col.f32.f16.f16.f32 "
                 "{%0,%1,%2,%3}, {%4,%5,%6,%7}, {%8,%9}, {%0,%1,%2,%3};"
                 : "+f"(d[0]), "+f"(d[1]), "+f"(d[2]), "+f"(d[3])
                 : "r"(a[0]), "r"(a[1]), "r"(a[2]), "r"(a[3]), "r"(b0), "r"(b1));
}

// fp32x4 -> fp16x4 (8B)
__device__ __forceinline__ void cvt4h(float4 v, char* p) {
    __half2 h01 = __floats2half2_rn(v.x, v.y);
    __half2 h23 = __floats2half2_rn(v.z, v.w);
    uint2 u;
    u.x = *reinterpret_cast<uint32_t*>(&h01);
    u.y = *reinterpret_cast<uint32_t*>(&h23);
    *reinterpret_cast<uint2*>(p) = u;
}

// fp32x4 -> fp16 hi/lo planes (8B each)
__device__ __forceinline__ void split4h(float4 v, char* hp, char* lp) {
    __half2 h01 = __floats2half2_rn(v.x, v.y);
    __half2 h23 = __floats2half2_rn(v.z, v.w);
    float2 f01 = __half22float2(h01);
    float2 f23 = __half22float2(h23);
    __half2 l01 = __floats2half2_rn(v.x - f01.x, v.y - f01.y);
    __half2 l23 = __floats2half2_rn(v.z - f23.x, v.w - f23.y);
    uint2 hv, lv;
    hv.x = *reinterpret_cast<uint32_t*>(&h01);
    hv.y = *reinterpret_cast<uint32_t*>(&h23);
    lv.x = *reinterpret_cast<uint32_t*>(&l01);
    lv.y = *reinterpret_cast<uint32_t*>(&l23);
    *reinterpret_cast<uint2*>(hp) = hv;
    *reinterpret_cast<uint2*>(lp) = lv;
}

// ---------------- elementwise kernels ----------------
__global__ void zero_stats_kernel(int n) {
    int i = blockIdx.x * blockDim.x + threadIdx.x;
    if (i < n) { g_sum[i] = 0.f; g_sumsq[i] = 0.f; }
}

__global__ void finalize_stats_kernel(const float* __restrict__ gamma,
                                      const float* __restrict__ beta,
                                      int N, float invM) {
    int i = blockIdx.x * blockDim.x + threadIdx.x;
    if (i >= N) return;
    float mu  = g_sum[i] * invM;
    float var = g_sumsq[i] * invM - mu * mu;
    float sc  = gamma[i] * rsqrtf(var + EPS);
    g_scale[i] = sc;
    g_shift[i] = beta[i] - mu * sc;
}

// W (K,N) fp32 -> fp16 hi/lo planes, same layout
__global__ void wsplit_kernel(const float* __restrict__ W,
                              __half* __restrict__ hi, __half* __restrict__ lo,
                              long long total4) {
    for (long long i = (long long)blockIdx.x * blockDim.x + threadIdx.x;
         i < total4; i += (long long)gridDim.x * blockDim.x) {
        float4 v = *(const float4*)(W + i * 4);
        split4h(v, (char*)(hi + i * 4), (char*)(lo + i * 4));
    }
}

// ---------------- HMMA GEMM (fp16 2-product) ----------------
// C = f(A) @ W + bias.  A fp32 -> fp16 in-kernel; W pre-split fp16 hi/lo (K,N).
// BM=128, BN=128, BK=32; 256 threads (8 warps, 2x4), warp tile 64x32.
// CAT: A row r = concat(left[r, 0:Cl], right[gather(r), 0:Cl]); K = 2*Cl.
// NORM: BN normalize+ReLU on A. STATS: column sum/sumsq of C.
template <bool NORM, bool STATS, bool CAT>
__global__ __launch_bounds__(256, 2)
void hmma_gemm_kernel(const float* __restrict__ Aleft, const float* __restrict__ Aright,
                      const int* __restrict__ gidx, int outRPB, int srcRPB,
                      const __half* __restrict__ Wh, const __half* __restrict__ Wl,
                      const float* __restrict__ bias, float* __restrict__ C,
                      int M, int N, int K) {
    constexpr int A_STR = 80;                 // bytes per A smem row (32 fp16 + pad)
    constexpr int W_STR = 272;                // bytes per W smem row (128 fp16 + pad)
    constexpr int A_PLANE = 128 * A_STR;      // 10240
    constexpr int W_PLANE = 32 * W_STR;       // 8704
    constexpr int OFF_A  = 0;
    constexpr int OFF_WH = A_PLANE;
    constexpr int OFF_WL = A_PLANE + W_PLANE;
    constexpr int STAGE = A_PLANE + 2 * W_PLANE;   // 27648

    extern __shared__ char sm[];
    const uint32_t smb = smem_u32(sm);

    const int tid = threadIdx.x;
    const int wid = tid >> 5;
    const int lane = tid & 31;
    const int warp_m = (wid >> 2) * 64;
    const int warp_n = (wid & 3) * 32;
    const int bm0 = blockIdx.y * 128;
    const int bn0 = blockIdx.x * 128;
    const int T = K >> 5;
    const int Cl = K >> 1;                    // only used when CAT

    // A fp32 LDG mapping: 128x32 = 1024 float4, 4 per thread
    int a_row[4], a_c[4];
    uint32_t a_soff[4];
    const float* rowL[4];
    const float* rowR[4];
#pragma unroll
    for (int i = 0; i < 4; i++) {
        int idx = tid + (i << 8);
        a_row[i] = idx >> 3;
        a_c[i] = (idx & 7) << 2;
        a_soff[i] = a_row[i] * A_STR + a_c[i] * 2;
        int r = bm0 + a_row[i];
        if (CAT) {
            int b = r / outRPB;
            int src = b * srcRPB + gidx[r];
            rowL[i] = Aleft + (size_t)r * Cl;
            rowR[i] = Aright + (size_t)src * Cl;
        } else {
            rowL[i] = Aleft + (size_t)r * K;
            rowR[i] = nullptr;
        }
    }
    // W cp.async mapping: per plane 512 x 16B chunks, 2 per thread
    int wRow[2], wCol[2];
    uint32_t wS[2];
#pragma unroll
    for (int i = 0; i < 2; i++) {
        int c = tid + (i << 8);
        wRow[i] = c >> 4;
        wCol[i] = (c & 15) * 8;
        wS[i] = wRow[i] * W_STR + (c & 15) * 16;
    }

    // ldmatrix offsets (stage-relative)
    uint32_t a_off[4], b_off[2];
#pragma unroll
    for (int mt = 0; mt < 4; mt++)
        a_off[mt] = (uint32_t)((warp_m + mt * 16 + (lane & 15)) * A_STR + ((lane >> 4) << 3) * 2);
#pragma unroll
    for (int np = 0; np < 2; np++)
        b_off[np] = (uint32_t)((lane & 15) * W_STR + (warp_n + np * 16 + ((lane >> 4) << 3)) * 2);

    float acc[4][4][4];
#pragma unroll
    for (int mt = 0; mt < 4; mt++)
#pragma unroll
        for (int nt = 0; nt < 4; nt++)
#pragma unroll
            for (int q = 0; q < 4; q++) acc[mt][nt][q] = 0.f;

    float4 ar[4];

    // A source load for tile starting at k0
    auto loadA = [&](int k0, int i) -> float4 {
        int col = k0 + a_c[i];
        if (CAT) {
            return (col < Cl) ? *(const float4*)(rowL[i] + col)
                              : *(const float4*)(rowR[i] + (col - Cl));
        }
        return *(const float4*)(rowL[i] + col);
    };

    // ---- prologue: W cp stage0, A ldg+convert stage0 ----
    {
#pragma unroll
        for (int i = 0; i < 2; i++) {
            size_t gw = (size_t)wRow[i] * N + bn0 + wCol[i];
            cp16(smb + OFF_WH + wS[i], Wh + gw);
            cp16(smb + OFF_WL + wS[i], Wl + gw);
        }
        CP_COMMIT();
#pragma unroll
        for (int i = 0; i < 4; i++)
            ar[i] = loadA(0, i);
#pragma unroll
        for (int i = 0; i < 4; i++) {
            float4 v = ar[i];
            if (NORM) {
                float4 sc = *(const float4*)(g_scale + a_c[i]);
                float4 sh = *(const float4*)(g_shift + a_c[i]);
                v.x = fmaxf(v.x * sc.x + sh.x, 0.f);
                v.y = fmaxf(v.y * sc.y + sh.y, 0.f);
                v.z = fmaxf(v.z * sc.z + sh.z, 0.f);
                v.w = fmaxf(v.w * sc.w + sh.w, 0.f);
            }
            cvt4h(v, sm + OFF_A + a_soff[i]);
        }
        CP_WAIT0();
    }
    __syncthreads();

    for (int t = 0; t < T; t++) {
        const int s = t & 1;
        const uint32_t sbase = smb + s * STAGE;
        const bool has_next = (t + 1 < T);
        const int k0n = (t + 1) << 5;

        if (has_next) {
            uint32_t nb = smb + (s ^ 1) * STAGE;
#pragma unroll
            for (int i = 0; i < 2; i++) {
                size_t gw = (size_t)(k0n + wRow[i]) * N + bn0 + wCol[i];
                cp16(nb + OFF_WH + wS[i], Wh + gw);
                cp16(nb + OFF_WL + wS[i], Wl + gw);
            }
            CP_COMMIT();
#pragma unroll
            for (int i = 0; i < 4; i++)
                ar[i] = loadA(k0n, i);
        }

#pragma unroll
        for (int ks = 0; ks < 2; ks++) {
            uint32_t ah[4][4];
#pragma unroll
            for (int mt = 0; mt < 4; mt++)
                ldsm_x4(ah[mt], sbase + OFF_A + a_off[mt] + ks * 32);
#pragma unroll
            for (int np = 0; np < 2; np++) {
                uint32_t bh[4], bl[4];
                ldsm_x4_t(bh, sbase + OFF_WH + b_off[np] + ks * (16 * W_STR));
                ldsm_x4_t(bl, sbase + OFF_WL + b_off[np] + ks * (16 * W_STR));
#pragma unroll
                for (int mt = 0; mt < 4; mt++)
#pragma unroll
                    for (int half = 0; half < 2; half++)
                        mma16816(acc[mt][np * 2 + half], ah[mt], bh[half * 2], bh[half * 2 + 1]);
#pragma unroll
                for (int mt = 0; mt < 4; mt++)
#pragma unroll
                    for (int half = 0; half < 2; half++)
                        mma16816(acc[mt][np * 2 + half], ah[mt], bl[half * 2], bl[half * 2 + 1]);
            }
        }

        if (has_next) {
            char* nb = sm + (s ^ 1) * STAGE;
#pragma unroll
            for (int i = 0; i < 4; i++) {
                float4 v = ar[i];
                if (NORM) {
                    float4 sc = *(const float4*)(g_scale + k0n + a_c[i]);
                    float4 sh = *(const float4*)(g_shift + k0n + a_c[i]);
                    v.x = fmaxf(v.x * sc.x + sh.x, 0.f);
                    v.y = fmaxf(v.y * sc.y + sh.y, 0.f);
                    v.z = fmaxf(v.z * sc.z + sh.z, 0.f);
                    v.w = fmaxf(v.w * sc.w + sh.w, 0.f);
                }
                cvt4h(v, nb + OFF_A + a_soff[i]);
            }
            CP_WAIT0();
        }
        __syncthreads();
    }

    // ---- epilogue: bias + store (+ column stats) ----
#pragma unroll
    for (int nt = 0; nt < 4; nt++) {
        int c0 = bn0 + warp_n + (nt >> 1) * 16 + (nt & 1) * 8 + (lane & 3) * 2;
        float b0 = bias[c0], b1 = bias[c0 + 1];
        float s0 = 0.f, s1 = 0.f, q0 = 0.f, q1 = 0.f;
#pragma unroll
        for (int mt = 0; mt < 4; mt++) {
            int r0 = bm0 + warp_m + mt * 16 + (lane >> 2);
            float v0 = acc[mt][nt][0] + b0, v1 = acc[mt][nt][1] + b1;
            float v2 = acc[mt][nt][2] + b0, v3 = acc[mt][nt][3] + b1;
            float2 p0; p0.x = v0; p0.y = v1;
            float2 p1; p1.x = v2; p1.y = v3;
            *(float2*)(C + (size_t)r0 * N + c0) = p0;
            *(float2*)(C + (size_t)(r0 + 8) * N + c0) = p1;
            if (STATS) {
                s0 += v0 + v2; s1 += v1 + v3;
                q0 += v0 * v0 + v2 * v2; q1 += v1 * v1 + v3 * v3;
            }
        }
        if (STATS) {
#pragma unroll
            for (int off = 4; off < 32; off <<= 1) {
                s0 += __shfl_xor_sync(0xFFFFFFFFu, s0, off);
                s1 += __shfl_xor_sync(0xFFFFFFFFu, s1, off);
                q0 += __shfl_xor_sync(0xFFFFFFFFu, q0, off);
                q1 += __shfl_xor_sync(0xFFFFFFFFu, q1, off);
            }
            if ((lane >> 2) == 0) {
                atomicAdd(&g_sum[c0], s0);
                atomicAdd(&g_sum[c0 + 1], s1);
                atomicAdd(&g_sumsq[c0], q0);
                atomicAdd(&g_sumsq[c0 + 1], q1);
            }
        }
    }
}

// ---------------- host orchestration ----------------
static const int GEMM_SMEM = 2 * 27648;   // 55296

static __half *s_whi, *s_wlo;
static float *s_bufA, *s_bufB;

// plain GEMM (optionally NORM / STATS)
template <bool NORM, bool STATS>
static void run_gemm(const float* A, size_t woff, const float* bias, float* C,
                     int M, int N, int K) {
    dim3 grid(N / 128, M / 128);
    hmma_gemm_kernel<NORM, STATS, false><<<grid, 256, GEMM_SMEM>>>(
        A, nullptr, nullptr, 1, 1, s_whi + woff, s_wlo + woff, bias, C, M, N, K);
}

// fused gather+concat GEMM (STATS always on: these are GEMM1s)
static void run_gemm_cat(const float* left, const float* right, const int* gidx,
                         int outRPB, int srcRPB, size_t woff,
                         const float* bias, float* C, int M, int N, int K) {
    dim3 grid(N / 128, M / 128);
    hmma_gemm_kernel<false, true, true><<<grid, 256, GEMM_SMEM>>>(
        left, right, gidx, outRPB, srcRPB, s_whi + woff, s_wlo + woff, bias, C, M, N, K);
}

extern "C" void kernel_launch(void* const* d_in, const int* in_sizes, int n_in,
                              void* d_out, int out_size) {
    const float* f0 = (const float*)d_in[0];
    const float* f1 = (const float*)d_in[1];
    const float* f2 = (const float*)d_in[2];
    const float* up0_w1 = (const float*)d_in[3];
    const float* up0_b1 = (const float*)d_in[4];
    const float* up0_g  = (const float*)d_in[5];
    const float* up0_be = (const float*)d_in[6];
    const float* up0_w2 = (const float*)d_in[7];
    const float* up0_b2 = (const float*)d_in[8];
    const float* up1_w1 = (const float*)d_in[9];
    const float* up1_b1 = (const float*)d_in[10];
    const float* up1_g  = (const float*)d_in[11];
    const float* up1_be = (const float*)d_in[12];
    const float* up1_w2 = (const float*)d_in[13];
    const float* up1_b2 = (const float*)d_in[14];
    const float* skip0_w1 = (const float*)d_in[15];
    const float* skip0_b1 = (const float*)d_in[16];
    const float* skip0_g  = (const float*)d_in[17];
    const float* skip0_be = (const float*)d_in[18];
    const float* skip0_w2 = (const float*)d_in[19];
    const float* skip0_b2 = (const float*)d_in[20];
    const float* skip1_w1 = (const float*)d_in[21];
    const float* skip1_b1 = (const float*)d_in[22];
    const float* skip1_g  = (const float*)d_in[23];
    const float* skip1_be = (const float*)d_in[24];
    const float* skip1_w2 = (const float*)d_in[25];
    const float* skip1_b2 = (const float*)d_in[26];
    const int*   pool0 = (const int*)d_in[27];
    const int*   pool1 = (const int*)d_in[28];
    float* out = (float*)d_out;

    cudaGetSymbolAddress((void**)&s_bufA, g_bufA);
    cudaGetSymbolAddress((void**)&s_bufB, g_bufB);
    cudaGetSymbolAddress((void**)&s_whi, g_whi);
    cudaGetSymbolAddress((void**)&s_wlo, g_wlo);

    cudaFuncSetAttribute(hmma_gemm_kernel<false, true, false>, cudaFuncAttributeMaxDynamicSharedMemorySize, GEMM_SMEM);
    cudaFuncSetAttribute(hmma_gemm_kernel<true, false, false>, cudaFuncAttributeMaxDynamicSharedMemorySize, GEMM_SMEM);
    cudaFuncSetAttribute(hmma_gemm_kernel<false, true, true>,  cudaFuncAttributeMaxDynamicSharedMemorySize, GEMM_SMEM);

    const int B = 4;
    const int N0 = 32768, N1 = 8192, N2 = 2048;
    const int C0 = 256, C1 = 512, C2 = 1024;
    const int M_u1 = B * N2, M_s1 = B * N1, M_s0 = B * N0;

    // weight plane offsets (K,N) layout
    const size_t O_U1W1 = 0;
    const size_t O_U1W2 = 1048576;
    const size_t O_S1W1 = 1572864;
    const size_t O_S1W2 = 2621440;
    const size_t O_U0W1 = 3145728;
    const size_t O_U0W2 = 3407872;
    const size_t O_S0W1 = 3538944;
    const size_t O_S0W2 = 3801088;

    // ---- up1 MLP: f2 (8192,1024) -> 1024 -> 512 ----
    zero_stats_kernel<<<4, 256>>>(1024);
    wsplit_kernel<<<512, 256>>>(up1_w1, s_whi + O_U1W1, s_wlo + O_U1W1, (long long)C2 * C2 / 4);
    wsplit_kernel<<<512, 256>>>(up1_w2, s_whi + O_U1W2, s_wlo + O_U1W2, (long long)C2 * C1 / 4);
    run_gemm<false, true>(f2, O_U1W1, up1_b1, s_bufA, M_u1, C2, C2);     // profiled slot
    finalize_stats_kernel<<<4, 256>>>(up1_g, up1_be, C2, 1.0f / M_u1);
    run_gemm<true, false>(s_bufA, O_U1W2, up1_b2, s_bufB, M_u1, C1, C2);

    // ---- skip1 MLP: concat(f1, gather(bufB, pool1)) (32768,1024) -> 1024 -> 512 ----
    zero_stats_kernel<<<4, 256>>>(1024);
    wsplit_kernel<<<512, 256>>>(skip1_w1, s_whi + O_S1W1, s_wlo + O_S1W1, (long long)(2 * C1) * (2 * C1) / 4);
    wsplit_kernel<<<512, 256>>>(skip1_w2, s_whi + O_S1W2, s_wlo + O_S1W2, (long long)(2 * C1) * C1 / 4);
    run_gemm_cat(f1, s_bufB, pool1, N1, N2, O_S1W1, skip1_b1, s_bufA, M_s1, 2 * C1, 2 * C1);
    finalize_stats_kernel<<<4, 256>>>(skip1_g, skip1_be, 2 * C1, 1.0f / M_s1);
    run_gemm<true, false>(s_bufA, O_S1W2, skip1_b2, s_bufB, M_s1, C1, 2 * C1);

    // ---- up0 MLP: (32768,512) -> 512 -> 256 ----
    zero_stats_kernel<<<2, 256>>>(512);
    wsplit_kernel<<<256, 256>>>(up0_w1, s_whi + O_U0W1, s_wlo + O_U0W1, (long long)C1 * C1 / 4);
    wsplit_kernel<<<256, 256>>>(up0_w2, s_whi + O_U0W2, s_wlo + O_U0W2, (long long)C1 * C0 / 4);
    run_gemm<false, true>(s_bufB, O_U0W1, up0_b1, s_bufA, M_s1, C1, C1);
    finalize_stats_kernel<<<2, 256>>>(up0_g, up0_be, C1, 1.0f / M_s1);
    run_gemm<true, false>(s_bufA, O_U0W2, up0_b2, s_bufB, M_s1, C0, C1);

    // ---- skip0 MLP: concat(f0, gather(bufB, pool0)) (131072,512) -> 512 -> 256 -> out ----
    zero_stats_kernel<<<2, 256>>>(512);
    wsplit_kernel<<<256, 256>>>(skip0_w1, s_whi + O_S0W1, s_wlo + O_S0W1, (long long)(2 * C0) * (2 * C0) / 4);
    wsplit_kernel<<<256, 256>>>(skip0_w2, s_whi + O_S0W2, s_wlo + O_S0W2, (long long)(2 * C0) * C0 / 4);
    run_gemm_cat(f0, s_bufB, pool0, N0, N1, O_S0W1, skip0_b1, s_bufA, M_s0, 2 * C0, 2 * C0);
    finalize_stats_kernel<<<2, 256>>>(skip0_g, skip0_be, 2 * C0, 1.0f / M_s0);
    run_gemm<true, false>(s_bufA, O_S0W2, skip0_b2, out, M_s0, C0, 2 * C0);
}

// round 12
// speedup vs baseline: 2.2131x; 1.4775x over previous
#include <cuda_runtime.h>
#include <cuda_fp16.h>
#include <cstdint>
#include <math.h>

#define EPS 1e-5f

// ---------------- scratch (device globals) ----------------
__device__ float g_bufA[67108864];               // GEMM1 H outputs (max 131072x512)
__device__ float g_bufB[16777216];               // GEMM2 outputs (max 32768x512)
__device__ __half g_wh[4194304];                 // weight fp16 planes (all 8 GEMMs)
__device__ float g_sum[1024];
__device__ float g_sumsq[1024];
__device__ float g_scale[1024];
__device__ float g_shift[1024];

// ---------------- PTX helpers ----------------
__device__ __forceinline__ uint32_t smem_u32(const void* p) {
    uint32_t a;
    asm("{ .reg .u64 t; cvta.to.shared.u64 t, %1; cvt.u32.u64 %0, t; }" : "=r"(a) : "l"(p));
    return a;
}
__device__ __forceinline__ void cp16(uint32_t sdst, const void* gsrc) {
    asm volatile("cp.async.cg.shared.global [%0], [%1], 16;" :: "r"(sdst), "l"(gsrc));
}
#define CP_COMMIT() asm volatile("cp.async.commit_group;" ::: "memory")
#define CP_WAIT0()  asm volatile("cp.async.wait_group 0;" ::: "memory")

__device__ __forceinline__ void ldsm_x4(uint32_t* r, uint32_t addr) {
    asm volatile("ldmatrix.sync.aligned.m8n8.x4.shared.b16 {%0,%1,%2,%3}, [%4];"
                 : "=r"(r[0]), "=r"(r[1]), "=r"(r[2]), "=r"(r[3]) : "r"(addr));
}
__device__ __forceinline__ void ldsm_x4_t(uint32_t* r, uint32_t addr) {
    asm volatile("ldmatrix.sync.aligned.m8n8.x4.trans.shared.b16 {%0,%1,%2,%3}, [%4];"
                 : "=r"(r[0]), "=r"(r[1]), "=r"(r[2]), "=r"(r[3]) : "r"(addr));
}
__device__ __forceinline__ void mma16816(float* d, const uint32_t* a, uint32_t b0, uint32_t b1) {
    asm volatile("mma.sync.aligned.m16n8k16.row.col.f32.f16.f16.f32 "
                 "{%0,%1,%2,%3}, {%4,%5,%6,%7}, {%8,%9}, {%0,%1,%2,%3};"
                 : "+f"(d[0]), "+f"(d[1]), "+f"(d[2]), "+f"(d[3])
                 : "r"(a[0]), "r"(a[1]), "r"(a[2]), "r"(a[3]), "r"(b0), "r"(b1));
}

// fp32x4 -> fp16x4 (8B)
__device__ __forceinline__ void cvt4h(float4 v, char* p) {
    __half2 h01 = __floats2half2_rn(v.x, v.y);
    __half2 h23 = __floats2half2_rn(v.z, v.w);
    uint2 u;
    u.x = *reinterpret_cast<uint32_t*>(&h01);
    u.y = *reinterpret_cast<uint32_t*>(&h23);
    *reinterpret_cast<uint2*>(p) = u;
}

// ---------------- elementwise kernels ----------------
__global__ void zero_stats_kernel(int n) {
    int i = blockIdx.x * blockDim.x + threadIdx.x;
    if (i < n) { g_sum[i] = 0.f; g_sumsq[i] = 0.f; }
}

__global__ void finalize_stats_kernel(const float* __restrict__ gamma,
                                      const float* __restrict__ beta,
                                      int N, float invM) {
    int i = blockIdx.x * blockDim.x + threadIdx.x;
    if (i >= N) return;
    float mu  = g_sum[i] * invM;
    float var = g_sumsq[i] * invM - mu * mu;
    float sc  = gamma[i] * rsqrtf(var + EPS);
    g_scale[i] = sc;
    g_shift[i] = beta[i] - mu * sc;
}

// W (K,N) fp32 -> fp16 plane, same layout
__global__ void wcvt_kernel(const float* __restrict__ W,
                            __half* __restrict__ hp, long long total4) {
    for (long long i = (long long)blockIdx.x * blockDim.x + threadIdx.x;
         i < total4; i += (long long)gridDim.x * blockDim.x) {
        float4 v = *(const float4*)(W + i * 4);
        cvt4h(v, (char*)(hp + i * 4));
    }
}

// ---------------- HMMA GEMM (fp16 single-product) ----------------
// C = f(A) @ W + bias.  A fp32 -> fp16 in-kernel; W pre-converted fp16 (K,N).
// BM=128, BN=128, BK=32; 256 threads (8 warps, 2x4), warp tile 64x32.
// CAT: A row r = concat(left[r, 0:Cl], right[gather(r), 0:Cl]); K = 2*Cl.
// NORM: BN normalize+ReLU on A. STATS: column sum/sumsq of C.
template <bool NORM, bool STATS, bool CAT>
__global__ __launch_bounds__(256, 2)
void hmma_gemm_kernel(const float* __restrict__ Aleft, const float* __restrict__ Aright,
                      const int* __restrict__ gidx, int outRPB, int srcRPB,
                      const __half* __restrict__ Wh,
                      const float* __restrict__ bias, float* __restrict__ C,
                      int M, int N, int K) {
    constexpr int A_STR = 80;                 // bytes per A smem row (32 fp16 + pad)
    constexpr int W_STR = 272;                // bytes per W smem row (128 fp16 + pad)
    constexpr int A_PLANE = 128 * A_STR;      // 10240
    constexpr int W_PLANE = 32 * W_STR;       // 8704
    constexpr int OFF_A  = 0;
    constexpr int OFF_WH = A_PLANE;
    constexpr int STAGE = A_PLANE + W_PLANE;  // 18944

    extern __shared__ char sm[];
    const uint32_t smb = smem_u32(sm);

    const int tid = threadIdx.x;
    const int wid = tid >> 5;
    const int lane = tid & 31;
    const int warp_m = (wid >> 2) * 64;
    const int warp_n = (wid & 3) * 32;
    const int bm0 = blockIdx.y * 128;
    const int bn0 = blockIdx.x * 128;
    const int T = K >> 5;
    const int Cl = K >> 1;                    // only used when CAT

    // A fp32 LDG mapping: 128x32 = 1024 float4, 4 per thread
    int a_row[4], a_c[4];
    uint32_t a_soff[4];
    const float* rowL[4];
    const float* rowR[4];
#pragma unroll
    for (int i = 0; i < 4; i++) {
        int idx = tid + (i << 8);
        a_row[i] = idx >> 3;
        a_c[i] = (idx & 7) << 2;
        a_soff[i] = a_row[i] * A_STR + a_c[i] * 2;
        int r = bm0 + a_row[i];
        if (CAT) {
            int b = r / outRPB;
            int src = b * srcRPB + gidx[r];
            rowL[i] = Aleft + (size_t)r * Cl;
            rowR[i] = Aright + (size_t)src * Cl;
        } else {
            rowL[i] = Aleft + (size_t)r * K;
            rowR[i] = nullptr;
        }
    }
    // W cp.async mapping: 512 x 16B chunks, 2 per thread
    int wRow[2], wCol[2];
    uint32_t wS[2];
#pragma unroll
    for (int i = 0; i < 2; i++) {
        int c = tid + (i << 8);
        wRow[i] = c >> 4;
        wCol[i] = (c & 15) * 8;
        wS[i] = wRow[i] * W_STR + (c & 15) * 16;
    }

    // ldmatrix offsets (stage-relative)
    uint32_t a_off[4], b_off[2];
#pragma unroll
    for (int mt = 0; mt < 4; mt++)
        a_off[mt] = (uint32_t)((warp_m + mt * 16 + (lane & 15)) * A_STR + ((lane >> 4) << 3) * 2);
#pragma unroll
    for (int np = 0; np < 2; np++)
        b_off[np] = (uint32_t)((lane & 15) * W_STR + (warp_n + np * 16 + ((lane >> 4) << 3)) * 2);

    float acc[4][4][4];
#pragma unroll
    for (int mt = 0; mt < 4; mt++)
#pragma unroll
        for (int nt = 0; nt < 4; nt++)
#pragma unroll
            for (int q = 0; q < 4; q++) acc[mt][nt][q] = 0.f;

    float4 ar[4];

    auto loadA = [&](int k0, int i) -> float4 {
        int col = k0 + a_c[i];
        if (CAT) {
            return (col < Cl) ? *(const float4*)(rowL[i] + col)
                              : *(const float4*)(rowR[i] + (col - Cl));
        }
        return *(const float4*)(rowL[i] + col);
    };

    // ---- prologue ----
    {
#pragma unroll
        for (int i = 0; i < 2; i++) {
            size_t gw = (size_t)wRow[i] * N + bn0 + wCol[i];
            cp16(smb + OFF_WH + wS[i], Wh + gw);
        }
        CP_COMMIT();
#pragma unroll
        for (int i = 0; i < 4; i++)
            ar[i] = loadA(0, i);
#pragma unroll
        for (int i = 0; i < 4; i++) {
            float4 v = ar[i];
            if (NORM) {
                float4 sc = *(const float4*)(g_scale + a_c[i]);
                float4 sh = *(const float4*)(g_shift + a_c[i]);
                v.x = fmaxf(v.x * sc.x + sh.x, 0.f);
                v.y = fmaxf(v.y * sc.y + sh.y, 0.f);
                v.z = fmaxf(v.z * sc.z + sh.z, 0.f);
                v.w = fmaxf(v.w * sc.w + sh.w, 0.f);
            }
            cvt4h(v, sm + OFF_A + a_soff[i]);
        }
        CP_WAIT0();
    }
    __syncthreads();

    for (int t = 0; t < T; t++) {
        const int s = t & 1;
        const uint32_t sbase = smb + s * STAGE;
        const bool has_next = (t + 1 < T);
        const int k0n = (t + 1) << 5;

        if (has_next) {
            uint32_t nb = smb + (s ^ 1) * STAGE;
#pragma unroll
            for (int i = 0; i < 2; i++) {
                size_t gw = (size_t)(k0n + wRow[i]) * N + bn0 + wCol[i];
                cp16(nb + OFF_WH + wS[i], Wh + gw);
            }
            CP_COMMIT();
#pragma unroll
            for (int i = 0; i < 4; i++)
                ar[i] = loadA(k0n, i);
        }

#pragma unroll
        for (int ks = 0; ks < 2; ks++) {
            uint32_t ah[4][4];
#pragma unroll
            for (int mt = 0; mt < 4; mt++)
                ldsm_x4(ah[mt], sbase + OFF_A + a_off[mt] + ks * 32);
#pragma unroll
            for (int np = 0; np < 2; np++) {
                uint32_t bh[4];
                ldsm_x4_t(bh, sbase + OFF_WH + b_off[np] + ks * (16 * W_STR));
#pragma unroll
                for (int mt = 0; mt < 4; mt++)
#pragma unroll
                    for (int half = 0; half < 2; half++)
                        mma16816(acc[mt][np * 2 + half], ah[mt], bh[half * 2], bh[half * 2 + 1]);
            }
        }

        if (has_next) {
            char* nb = sm + (s ^ 1) * STAGE;
#pragma unroll
            for (int i = 0; i < 4; i++) {
                float4 v = ar[i];
                if (NORM) {
                    float4 sc = *(const float4*)(g_scale + k0n + a_c[i]);
                    float4 sh = *(const float4*)(g_shift + k0n + a_c[i]);
                    v.x = fmaxf(v.x * sc.x + sh.x, 0.f);
                    v.y = fmaxf(v.y * sc.y + sh.y, 0.f);
                    v.z = fmaxf(v.z * sc.z + sh.z, 0.f);
                    v.w = fmaxf(v.w * sc.w + sh.w, 0.f);
                }
                cvt4h(v, nb + OFF_A + a_soff[i]);
            }
            CP_WAIT0();
        }
        __syncthreads();
    }

    // ---- epilogue: bias + store (+ column stats) ----
#pragma unroll
    for (int nt = 0; nt < 4; nt++) {
        int c0 = bn0 + warp_n + (nt >> 1) * 16 + (nt & 1) * 8 + (lane & 3) * 2;
        float b0 = bias[c0], b1 = bias[c0 + 1];
        float s0 = 0.f, s1 = 0.f, q0 = 0.f, q1 = 0.f;
#pragma unroll
        for (int mt = 0; mt < 4; mt++) {
            int r0 = bm0 + warp_m + mt * 16 + (lane >> 2);
            float v0 = acc[mt][nt][0] + b0, v1 = acc[mt][nt][1] + b1;
            float v2 = acc[mt][nt][2] + b0, v3 = acc[mt][nt][3] + b1;
            float2 p0; p0.x = v0; p0.y = v1;
            float2 p1; p1.x = v2; p1.y = v3;
            *(float2*)(C + (size_t)r0 * N + c0) = p0;
            *(float2*)(C + (size_t)(r0 + 8) * N + c0) = p1;
            if (STATS) {
                s0 += v0 + v2; s1 += v1 + v3;
                q0 += v0 * v0 + v2 * v2; q1 += v1 * v1 + v3 * v3;
            }
        }
        if (STATS) {
#pragma unroll
            for (int off = 4; off < 32; off <<= 1) {
                s0 += __shfl_xor_sync(0xFFFFFFFFu, s0, off);
                s1 += __shfl_xor_sync(0xFFFFFFFFu, s1, off);
                q0 += __shfl_xor_sync(0xFFFFFFFFu, q0, off);
                q1 += __shfl_xor_sync(0xFFFFFFFFu, q1, off);
            }
            if ((lane >> 2) == 0) {
                atomicAdd(&g_sum[c0], s0);
                atomicAdd(&g_sum[c0 + 1], s1);
                atomicAdd(&g_sumsq[c0], q0);
                atomicAdd(&g_sumsq[c0 + 1], q1);
            }
        }
    }
}

// ---------------- host orchestration ----------------
static const int GEMM_SMEM = 2 * 18944;   // 37888

static __half *s_wh;
static float *s_bufA, *s_bufB;

template <bool NORM, bool STATS>
static void run_gemm(const float* A, size_t woff, const float* bias, float* C,
                     int M, int N, int K) {
    dim3 grid(N / 128, M / 128);
    hmma_gemm_kernel<NORM, STATS, false><<<grid, 256, GEMM_SMEM>>>(
        A, nullptr, nullptr, 1, 1, s_wh + woff, bias, C, M, N, K);
}

static void run_gemm_cat(const float* left, const float* right, const int* gidx,
                         int outRPB, int srcRPB, size_t woff,
                         const float* bias, float* C, int M, int N, int K) {
    dim3 grid(N / 128, M / 128);
    hmma_gemm_kernel<false, true, true><<<grid, 256, GEMM_SMEM>>>(
        left, right, gidx, outRPB, srcRPB, s_wh + woff, bias, C, M, N, K);
}

extern "C" void kernel_launch(void* const* d_in, const int* in_sizes, int n_in,
                              void* d_out, int out_size) {
    const float* f0 = (const float*)d_in[0];
    const float* f1 = (const float*)d_in[1];
    const float* f2 = (const float*)d_in[2];
    const float* up0_w1 = (const float*)d_in[3];
    const float* up0_b1 = (const float*)d_in[4];
    const float* up0_g  = (const float*)d_in[5];
    const float* up0_be = (const float*)d_in[6];
    const float* up0_w2 = (const float*)d_in[7];
    const float* up0_b2 = (const float*)d_in[8];
    const float* up1_w1 = (const float*)d_in[9];
    const float* up1_b1 = (const float*)d_in[10];
    const float* up1_g  = (const float*)d_in[11];
    const float* up1_be = (const float*)d_in[12];
    const float* up1_w2 = (const float*)d_in[13];
    const float* up1_b2 = (const float*)d_in[14];
    const float* skip0_w1 = (const float*)d_in[15];
    const float* skip0_b1 = (const float*)d_in[16];
    const float* skip0_g  = (const float*)d_in[17];
    const float* skip0_be = (const float*)d_in[18];
    const float* skip0_w2 = (const float*)d_in[19];
    const float* skip0_b2 = (const float*)d_in[20];
    const float* skip1_w1 = (const float*)d_in[21];
    const float* skip1_b1 = (const float*)d_in[22];
    const float* skip1_g  = (const float*)d_in[23];
    const float* skip1_be = (const float*)d_in[24];
    const float* skip1_w2 = (const float*)d_in[25];
    const float* skip1_b2 = (const float*)d_in[26];
    const int*   pool0 = (const int*)d_in[27];
    const int*   pool1 = (const int*)d_in[28];
    float* out = (float*)d_out;

    cudaGetSymbolAddress((void**)&s_bufA, g_bufA);
    cudaGetSymbolAddress((void**)&s_bufB, g_bufB);
    cudaGetSymbolAddress((void**)&s_wh, g_wh);

    cudaFuncSetAttribute(hmma_gemm_kernel<false, true, false>, cudaFuncAttributeMaxDynamicSharedMemorySize, GEMM_SMEM);
    cudaFuncSetAttribute(hmma_gemm_kernel<true, false, false>, cudaFuncAttributeMaxDynamicSharedMemorySize, GEMM_SMEM);
    cudaFuncSetAttribute(hmma_gemm_kernel<false, true, true>,  cudaFuncAttributeMaxDynamicSharedMemorySize, GEMM_SMEM);

    const int B = 4;
    const int N0 = 32768, N1 = 8192, N2 = 2048;
    const int C0 = 256, C1 = 512, C2 = 1024;
    const int M_u1 = B * N2, M_s1 = B * N1, M_s0 = B * N0;

    // weight plane offsets (K,N) layout
    const size_t O_U1W1 = 0;
    const size_t O_U1W2 = 1048576;
    const size_t O_S1W1 = 1572864;
    const size_t O_S1W2 = 2621440;
    const size_t O_U0W1 = 3145728;
    const size_t O_U0W2 = 3407872;
    const size_t O_S0W1 = 3538944;
    const size_t O_S0W2 = 3801088;

    // ---- up1 MLP: f2 (8192,1024) -> 1024 -> 512 ----
    zero_stats_kernel<<<4, 256>>>(1024);
    wcvt_kernel<<<512, 256>>>(up1_w1, s_wh + O_U1W1, (long long)C2 * C2 / 4);
    wcvt_kernel<<<512, 256>>>(up1_w2, s_wh + O_U1W2, (long long)C2 * C1 / 4);
    run_gemm<false, true>(f2, O_U1W1, up1_b1, s_bufA, M_u1, C2, C2);     // profiled slot
    finalize_stats_kernel<<<4, 256>>>(up1_g, up1_be, C2, 1.0f / M_u1);
    run_gemm<true, false>(s_bufA, O_U1W2, up1_b2, s_bufB, M_u1, C1, C2);

    // ---- skip1 MLP: concat(f1, gather(bufB, pool1)) (32768,1024) -> 1024 -> 512 ----
    zero_stats_kernel<<<4, 256>>>(1024);
    wcvt_kernel<<<512, 256>>>(skip1_w1, s_wh + O_S1W1, (long long)(2 * C1) * (2 * C1) / 4);
    wcvt_kernel<<<512, 256>>>(skip1_w2, s_wh + O_S1W2, (long long)(2 * C1) * C1 / 4);
    run_gemm_cat(f1, s_bufB, pool1, N1, N2, O_S1W1, skip1_b1, s_bufA, M_s1, 2 * C1, 2 * C1);
    finalize_stats_kernel<<<4, 256>>>(skip1_g, skip1_be, 2 * C1, 1.0f / M_s1);
    run_gemm<true, false>(s_bufA, O_S1W2, skip1_b2, s_bufB, M_s1, C1, 2 * C1);

    // ---- up0 MLP: (32768,512) -> 512 -> 256 ----
    zero_stats_kernel<<<2, 256>>>(512);
    wcvt_kernel<<<256, 256>>>(up0_w1, s_wh + O_U0W1, (long long)C1 * C1 / 4);
    wcvt_kernel<<<256, 256>>>(up0_w2, s_wh + O_U0W2, (long long)C1 * C0 / 4);
    run_gemm<false, true>(s_bufB, O_U0W1, up0_b1, s_bufA, M_s1, C1, C1);
    finalize_stats_kernel<<<2, 256>>>(up0_g, up0_be, C1, 1.0f / M_s1);
    run_gemm<true, false>(s_bufA, O_U0W2, up0_b2, s_bufB, M_s1, C0, C1);

    // ---- skip0 MLP: concat(f0, gather(bufB, pool0)) (131072,512) -> 512 -> 256 -> out ----
    zero_stats_kernel<<<2, 256>>>(512);
    wcvt_kernel<<<256, 256>>>(skip0_w1, s_wh + O_S0W1, (long long)(2 * C0) * (2 * C0) / 4);
    wcvt_kernel<<<256, 256>>>(skip0_w2, s_wh + O_S0W2, (long long)(2 * C0) * C0 / 4);
    run_gemm_cat(f0, s_bufB, pool0, N0, N1, O_S0W1, skip0_b1, s_bufA, M_s0, 2 * C0, 2 * C0);
    finalize_stats_kernel<<<2, 256>>>(skip0_g, skip0_be, 2 * C0, 1.0f / M_s0);
    run_gemm<true, false>(s_bufA, O_S0W2, skip0_b2, out, M_s0, C0, 2 * C0);
}

// round 13
// speedup vs baseline: 2.2165x; 1.0015x over previous
#include <cuda_runtime.h>
#include <cuda_fp16.h>
#include <cstdint>
#include <math.h>

#define EPS 1e-5f

// ---------------- scratch (device globals) ----------------
__device__ float g_bufA[67108864];               // GEMM1 H outputs (max 131072x512)
__device__ float g_bufB[16777216];               // GEMM2 outputs (max 32768x512)
__device__ __half g_wh[4194304];                 // weight fp16 planes (all 8 GEMMs)
__device__ float g_sum[1024];
__device__ float g_sumsq[1024];
__device__ float g_scale[1024];
__device__ float g_shift[1024];

// ---------------- PTX helpers ----------------
__device__ __forceinline__ uint32_t smem_u32(const void* p) {
    uint32_t a;
    asm("{ .reg .u64 t; cvta.to.shared.u64 t, %1; cvt.u32.u64 %0, t; }" : "=r"(a) : "l"(p));
    return a;
}
__device__ __forceinline__ void cp16(uint32_t sdst, const void* gsrc) {
    asm volatile("cp.async.cg.shared.global [%0], [%1], 16;" :: "r"(sdst), "l"(gsrc));
}
#define CP_COMMIT() asm volatile("cp.async.commit_group;" ::: "memory")
#define CP_WAIT0()  asm volatile("cp.async.wait_group 0;" ::: "memory")

__device__ __forceinline__ void ldsm_x4(uint32_t* r, uint32_t addr) {
    asm volatile("ldmatrix.sync.aligned.m8n8.x4.shared.b16 {%0,%1,%2,%3}, [%4];"
                 : "=r"(r[0]), "=r"(r[1]), "=r"(r[2]), "=r"(r[3]) : "r"(addr));
}
__device__ __forceinline__ void ldsm_x4_t(uint32_t* r, uint32_t addr) {
    asm volatile("ldmatrix.sync.aligned.m8n8.x4.trans.shared.b16 {%0,%1,%2,%3}, [%4];"
                 : "=r"(r[0]), "=r"(r[1]), "=r"(r[2]), "=r"(r[3]) : "r"(addr));
}
__device__ __forceinline__ void mma16816(float* d, const uint32_t* a, uint32_t b0, uint32_t b1) {
    asm volatile("mma.sync.aligned.m16n8k16.row.col.f32.f16.f16.f32 "
                 "{%0,%1,%2,%3}, {%4,%5,%6,%7}, {%8,%9}, {%0,%1,%2,%3};"
                 : "+f"(d[0]), "+f"(d[1]), "+f"(d[2]), "+f"(d[3])
                 : "r"(a[0]), "r"(a[1]), "r"(a[2]), "r"(a[3]), "r"(b0), "r"(b1));
}

// fp32x4 -> fp16x4 (8B)
__device__ __forceinline__ void cvt4h(float4 v, char* p) {
    __half2 h01 = __floats2half2_rn(v.x, v.y);
    __half2 h23 = __floats2half2_rn(v.z, v.w);
    uint2 u;
    u.x = *reinterpret_cast<uint32_t*>(&h01);
    u.y = *reinterpret_cast<uint32_t*>(&h23);
    *reinterpret_cast<uint2*>(p) = u;
}

// ---------------- elementwise kernels ----------------
__global__ void zero_stats_kernel(int n) {
    int i = blockIdx.x * blockDim.x + threadIdx.x;
    if (i < n) { g_sum[i] = 0.f; g_sumsq[i] = 0.f; }
}

__global__ void finalize_stats_kernel(const float* __restrict__ gamma,
                                      const float* __restrict__ beta,
                                      int N, float invM) {
    int i = blockIdx.x * blockDim.x + threadIdx.x;
    if (i >= N) return;
    float mu  = g_sum[i] * invM;
    float var = g_sumsq[i] * invM - mu * mu;
    float sc  = gamma[i] * rsqrtf(var + EPS);
    g_scale[i] = sc;
    g_shift[i] = beta[i] - mu * sc;
}

// W (K,N) fp32 -> fp16 plane, same layout
__global__ void wcvt_kernel(const float* __restrict__ W,
                            __half* __restrict__ hp, long long total4) {
    for (long long i = (long long)blockIdx.x * blockDim.x + threadIdx.x;
         i < total4; i += (long long)gridDim.x * blockDim.x) {
        float4 v = *(const float4*)(W + i * 4);
        cvt4h(v, (char*)(hp + i * 4));
    }
}

// ---------------- HMMA GEMM (fp16 single-product, 64x64 warp tile) ----------------
// C = f(A) @ W + bias.  A fp32 -> fp16 in-kernel; W pre-converted fp16 (K,N).
// BM=128, BN=128, BK=32; 128 threads (4 warps, 2x2), warp tile 64x64.
// CAT: A row r = concat(left[r, 0:Cl], right[gather(r), 0:Cl]); K = 2*Cl.
template <bool NORM, bool STATS, bool CAT>
__global__ __launch_bounds__(128, 2)
void hmma_gemm_kernel(const float* __restrict__ Aleft, const float* __restrict__ Aright,
                      const int* __restrict__ gidx, int outRPB, int srcRPB,
                      const __half* __restrict__ Wh,
                      const float* __restrict__ bias, float* __restrict__ C,
                      int M, int N, int K) {
    constexpr int A_STR = 80;                 // bytes per A smem row (32 fp16 + pad)
    constexpr int W_STR = 272;                // bytes per W smem row (128 fp16 + pad)
    constexpr int A_PLANE = 128 * A_STR;      // 10240
    constexpr int W_PLANE = 32 * W_STR;       // 8704
    constexpr int OFF_A  = 0;
    constexpr int OFF_WH = A_PLANE;
    constexpr int STAGE = A_PLANE + W_PLANE;  // 18944

    extern __shared__ char sm[];
    const uint32_t smb = smem_u32(sm);

    const int tid = threadIdx.x;
    const int wid = tid >> 5;
    const int lane = tid & 31;
    const int warp_m = (wid >> 1) * 64;       // 0 or 64
    const int warp_n = (wid & 1) * 64;        // 0 or 64
    const int bm0 = blockIdx.y * 128;
    const int bn0 = blockIdx.x * 128;
    const int T = K >> 5;
    const int Cl = K >> 1;                    // only used when CAT

    // A fp32 LDG mapping: 128x32 = 1024 float4, 8 per thread
    int a_c[8];
    uint32_t a_soff[8];
    int offL[8], offR[8];                     // element offsets into Aleft/Aright
#pragma unroll
    for (int i = 0; i < 8; i++) {
        int idx = tid + (i << 7);
        int arow = idx >> 3;
        a_c[i] = (idx & 7) << 2;
        a_soff[i] = arow * A_STR + a_c[i] * 2;
        int r = bm0 + arow;
        if (CAT) {
            int b = r / outRPB;
            int src = b * srcRPB + gidx[r];
            offL[i] = r * Cl;
            offR[i] = src * Cl;
        } else {
            offL[i] = r * K;
            offR[i] = 0;
        }
    }
    // W cp.async mapping: 512 x 16B chunks, 4 per thread
    int wRow[4], wCol[4];
    uint32_t wS[4];
#pragma unroll
    for (int i = 0; i < 4; i++) {
        int c = tid + (i << 7);
        wRow[i] = c >> 4;
        wCol[i] = (c & 15) * 8;
        wS[i] = wRow[i] * W_STR + (c & 15) * 16;
    }

    // ldmatrix offsets (stage-relative)
    uint32_t a_off[4], b_off[4];
#pragma unroll
    for (int mt = 0; mt < 4; mt++)
        a_off[mt] = (uint32_t)((warp_m + mt * 16 + (lane & 15)) * A_STR + ((lane >> 4) << 3) * 2);
#pragma unroll
    for (int np = 0; np < 4; np++)
        b_off[np] = (uint32_t)((lane & 15) * W_STR + (warp_n + np * 16 + ((lane >> 4) << 3)) * 2);

    float acc[4][8][4];
#pragma unroll
    for (int mt = 0; mt < 4; mt++)
#pragma unroll
        for (int nt = 0; nt < 8; nt++)
#pragma unroll
            for (int q = 0; q < 4; q++) acc[mt][nt][q] = 0.f;

    float4 ar[8];

    auto loadA = [&](int k0, int i) -> float4 {
        int col = k0 + a_c[i];
        if (CAT) {
            return (col < Cl) ? *(const float4*)(Aleft + offL[i] + col)
                              : *(const float4*)(Aright + offR[i] + (col - Cl));
        }
        return *(const float4*)(Aleft + offL[i] + col);
    };

    // ---- prologue ----
    {
#pragma unroll
        for (int i = 0; i < 4; i++) {
            size_t gw = (size_t)wRow[i] * N + bn0 + wCol[i];
            cp16(smb + OFF_WH + wS[i], Wh + gw);
        }
        CP_COMMIT();
#pragma unroll
        for (int i = 0; i < 8; i++)
            ar[i] = loadA(0, i);
#pragma unroll
        for (int i = 0; i < 8; i++) {
            float4 v = ar[i];
            if (NORM) {
                float4 sc = *(const float4*)(g_scale + a_c[i]);
                float4 sh = *(const float4*)(g_shift + a_c[i]);
                v.x = fmaxf(v.x * sc.x + sh.x, 0.f);
                v.y = fmaxf(v.y * sc.y + sh.y, 0.f);
                v.z = fmaxf(v.z * sc.z + sh.z, 0.f);
                v.w = fmaxf(v.w * sc.w + sh.w, 0.f);
            }
            cvt4h(v, sm + OFF_A + a_soff[i]);
        }
        CP_WAIT0();
    }
    __syncthreads();

    for (int t = 0; t < T; t++) {
        const int s = t & 1;
        const uint32_t sbase = smb + s * STAGE;
        const bool has_next = (t + 1 < T);
        const int k0n = (t + 1) << 5;

        if (has_next) {
            uint32_t nb = smb + (s ^ 1) * STAGE;
#pragma unroll
            for (int i = 0; i < 4; i++) {
                size_t gw = (size_t)(k0n + wRow[i]) * N + bn0 + wCol[i];
                cp16(nb + OFF_WH + wS[i], Wh + gw);
            }
            CP_COMMIT();
#pragma unroll
            for (int i = 0; i < 8; i++)
                ar[i] = loadA(k0n, i);
        }

#pragma unroll
        for (int ks = 0; ks < 2; ks++) {
            uint32_t ah[4][4];
#pragma unroll
            for (int mt = 0; mt < 4; mt++)
                ldsm_x4(ah[mt], sbase + OFF_A + a_off[mt] + ks * 32);
#pragma unroll
            for (int np = 0; np < 4; np++) {
                uint32_t bh[4];
                ldsm_x4_t(bh, sbase + OFF_WH + b_off[np] + ks * (16 * W_STR));
#pragma unroll
                for (int mt = 0; mt < 4; mt++)
#pragma unroll
                    for (int half = 0; half < 2; half++)
                        mma16816(acc[mt][np * 2 + half], ah[mt], bh[half * 2], bh[half * 2 + 1]);
            }
        }

        if (has_next) {
            char* nb = sm + (s ^ 1) * STAGE;
#pragma unroll
            for (int i = 0; i < 8; i++) {
                float4 v = ar[i];
                if (NORM) {
                    float4 sc = *(const float4*)(g_scale + k0n + a_c[i]);
                    float4 sh = *(const float4*)(g_shift + k0n + a_c[i]);
                    v.x = fmaxf(v.x * sc.x + sh.x, 0.f);
                    v.y = fmaxf(v.y * sc.y + sh.y, 0.f);
                    v.z = fmaxf(v.z * sc.z + sh.z, 0.f);
                    v.w = fmaxf(v.w * sc.w + sh.w, 0.f);
                }
                cvt4h(v, nb + OFF_A + a_soff[i]);
            }
            CP_WAIT0();
        }
        __syncthreads();
    }

    // ---- epilogue: bias + store (+ column stats) ----
    // nt -> col: c0 = bn0 + warp_n + (nt>>1)*16 + (nt&1)*8 + (lane&3)*2
#pragma unroll
    for (int nt = 0; nt < 8; nt++) {
        int c0 = bn0 + warp_n + (nt >> 1) * 16 + (nt & 1) * 8 + (lane & 3) * 2;
        float b0 = bias[c0], b1 = bias[c0 + 1];
        float s0 = 0.f, s1 = 0.f, q0 = 0.f, q1 = 0.f;
#pragma unroll
        for (int mt = 0; mt < 4; mt++) {
            int r0 = bm0 + warp_m + mt * 16 + (lane >> 2);
            float v0 = acc[mt][nt][0] + b0, v1 = acc[mt][nt][1] + b1;
            float v2 = acc[mt][nt][2] + b0, v3 = acc[mt][nt][3] + b1;
            float2 p0; p0.x = v0; p0.y = v1;
            float2 p1; p1.x = v2; p1.y = v3;
            *(float2*)(C + (size_t)r0 * N + c0) = p0;
            *(float2*)(C + (size_t)(r0 + 8) * N + c0) = p1;
            if (STATS) {
                s0 += v0 + v2; s1 += v1 + v3;
                q0 += v0 * v0 + v2 * v2; q1 += v1 * v1 + v3 * v3;
            }
        }
        if (STATS) {
#pragma unroll
            for (int off = 4; off < 32; off <<= 1) {
                s0 += __shfl_xor_sync(0xFFFFFFFFu, s0, off);
                s1 += __shfl_xor_sync(0xFFFFFFFFu, s1, off);
                q0 += __shfl_xor_sync(0xFFFFFFFFu, q0, off);
                q1 += __shfl_xor_sync(0xFFFFFFFFu, q1, off);
            }
            if ((lane >> 2) == 0) {
                atomicAdd(&g_sum[c0], s0);
                atomicAdd(&g_sum[c0 + 1], s1);
                atomicAdd(&g_sumsq[c0], q0);
                atomicAdd(&g_sumsq[c0 + 1], q1);
            }
        }
    }
}

// ---------------- host orchestration ----------------
static const int GEMM_SMEM = 2 * 18944;   // 37888

static __half *s_wh;
static float *s_bufA, *s_bufB;

template <bool NORM, bool STATS>
static void run_gemm(const float* A, size_t woff, const float* bias, float* C,
                     int M, int N, int K) {
    dim3 grid(N / 128, M / 128);
    hmma_gemm_kernel<NORM, STATS, false><<<grid, 128, GEMM_SMEM>>>(
        A, nullptr, nullptr, 1, 1, s_wh + woff, bias, C, M, N, K);
}

static void run_gemm_cat(const float* left, const float* right, const int* gidx,
                         int outRPB, int srcRPB, size_t woff,
                         const float* bias, float* C, int M, int N, int K) {
    dim3 grid(N / 128, M / 128);
    hmma_gemm_kernel<false, true, true><<<grid, 128, GEMM_SMEM>>>(
        left, right, gidx, outRPB, srcRPB, s_wh + woff, bias, C, M, N, K);
}

extern "C" void kernel_launch(void* const* d_in, const int* in_sizes, int n_in,
                              void* d_out, int out_size) {
    const float* f0 = (const float*)d_in[0];
    const float* f1 = (const float*)d_in[1];
    const float* f2 = (const float*)d_in[2];
    const float* up0_w1 = (const float*)d_in[3];
    const float* up0_b1 = (const float*)d_in[4];
    const float* up0_g  = (const float*)d_in[5];
    const float* up0_be = (const float*)d_in[6];
    const float* up0_w2 = (const float*)d_in[7];
    const float* up0_b2 = (const float*)d_in[8];
    const float* up1_w1 = (const float*)d_in[9];
    const float* up1_b1 = (const float*)d_in[10];
    const float* up1_g  = (const float*)d_in[11];
    const float* up1_be = (const float*)d_in[12];
    const float* up1_w2 = (const float*)d_in[13];
    const float* up1_b2 = (const float*)d_in[14];
    const float* skip0_w1 = (const float*)d_in[15];
    const float* skip0_b1 = (const float*)d_in[16];
    const float* skip0_g  = (const float*)d_in[17];
    const float* skip0_be = (const float*)d_in[18];
    const float* skip0_w2 = (const float*)d_in[19];
    const float* skip0_b2 = (const float*)d_in[20];
    const float* skip1_w1 = (const float*)d_in[21];
    const float* skip1_b1 = (const float*)d_in[22];
    const float* skip1_g  = (const float*)d_in[23];
    const float* skip1_be = (const float*)d_in[24];
    const float* skip1_w2 = (const float*)d_in[25];
    const float* skip1_b2 = (const float*)d_in[26];
    const int*   pool0 = (const int*)d_in[27];
    const int*   pool1 = (const int*)d_in[28];
    float* out = (float*)d_out;

    cudaGetSymbolAddress((void**)&s_bufA, g_bufA);
    cudaGetSymbolAddress((void**)&s_bufB, g_bufB);
    cudaGetSymbolAddress((void**)&s_wh, g_wh);

    cudaFuncSetAttribute(hmma_gemm_kernel<false, true, false>, cudaFuncAttributeMaxDynamicSharedMemorySize, GEMM_SMEM);
    cudaFuncSetAttribute(hmma_gemm_kernel<true, false, false>, cudaFuncAttributeMaxDynamicSharedMemorySize, GEMM_SMEM);
    cudaFuncSetAttribute(hmma_gemm_kernel<false, true, true>,  cudaFuncAttributeMaxDynamicSharedMemorySize, GEMM_SMEM);

    const int B = 4;
    const int N0 = 32768, N1 = 8192, N2 = 2048;
    const int C0 = 256, C1 = 512, C2 = 1024;
    const int M_u1 = B * N2, M_s1 = B * N1, M_s0 = B * N0;

    // weight plane offsets (K,N) layout
    const size_t O_U1W1 = 0;
    const size_t O_U1W2 = 1048576;
    const size_t O_S1W1 = 1572864;
    const size_t O_S1W2 = 2621440;
    const size_t O_U0W1 = 3145728;
    const size_t O_U0W2 = 3407872;
    const size_t O_S0W1 = 3538944;
    const size_t O_S0W2 = 3801088;

    // ---- up1 MLP: f2 (8192,1024) -> 1024 -> 512 ----
    zero_stats_kernel<<<4, 256>>>(1024);
    wcvt_kernel<<<512, 256>>>(up1_w1, s_wh + O_U1W1, (long long)C2 * C2 / 4);
    wcvt_kernel<<<512, 256>>>(up1_w2, s_wh + O_U1W2, (long long)C2 * C1 / 4);
    run_gemm<false, true>(f2, O_U1W1, up1_b1, s_bufA, M_u1, C2, C2);     // profiled slot
    finalize_stats_kernel<<<4, 256>>>(up1_g, up1_be, C2, 1.0f / M_u1);
    run_gemm<true, false>(s_bufA, O_U1W2, up1_b2, s_bufB, M_u1, C1, C2);

    // ---- skip1 MLP: concat(f1, gather(bufB, pool1)) (32768,1024) -> 1024 -> 512 ----
    zero_stats_kernel<<<4, 256>>>(1024);
    wcvt_kernel<<<512, 256>>>(skip1_w1, s_wh + O_S1W1, (long long)(2 * C1) * (2 * C1) / 4);
    wcvt_kernel<<<512, 256>>>(skip1_w2, s_wh + O_S1W2, (long long)(2 * C1) * C1 / 4);
    run_gemm_cat(f1, s_bufB, pool1, N1, N2, O_S1W1, skip1_b1, s_bufA, M_s1, 2 * C1, 2 * C1);
    finalize_stats_kernel<<<4, 256>>>(skip1_g, skip1_be, 2 * C1, 1.0f / M_s1);
    run_gemm<true, false>(s_bufA, O_S1W2, skip1_b2, s_bufB, M_s1, C1, 2 * C1);

    // ---- up0 MLP: (32768,512) -> 512 -> 256 ----
    zero_stats_kernel<<<2, 256>>>(512);
    wcvt_kernel<<<256, 256>>>(up0_w1, s_wh + O_U0W1, (long long)C1 * C1 / 4);
    wcvt_kernel<<<256, 256>>>(up0_w2, s_wh + O_U0W2, (long long)C1 * C0 / 4);
    run_gemm<false, true>(s_bufB, O_U0W1, up0_b1, s_bufA, M_s1, C1, C1);
    finalize_stats_kernel<<<2, 256>>>(up0_g, up0_be, C1, 1.0f / M_s1);
    run_gemm<true, false>(s_bufA, O_U0W2, up0_b2, s_bufB, M_s1, C0, C1);

    // ---- skip0 MLP: concat(f0, gather(bufB, pool0)) (131072,512) -> 512 -> 256 -> out ----
    zero_stats_kernel<<<2, 256>>>(512);
    wcvt_kernel<<<256, 256>>>(skip0_w1, s_wh + O_S0W1, (long long)(2 * C0) * (2 * C0) / 4);
    wcvt_kernel<<<256, 256>>>(skip0_w2, s_wh + O_S0W2, (long long)(2 * C0) * C0 / 4);
    run_gemm_cat(f0, s_bufB, pool0, N0, N1, O_S0W1, skip0_b1, s_bufA, M_s0, 2 * C0, 2 * C0);
    finalize_stats_kernel<<<2, 256>>>(skip0_g, skip0_be, 2 * C0, 1.0f / M_s0);
    run_gemm<true, false>(s_bufA, O_S0W2, skip0_b2, out, M_s0, C0, 2 * C0);
}

// round 14
// speedup vs baseline: 2.2236x; 1.0032x over previous
#include <cuda_runtime.h>
#include <cuda_fp16.h>
#include <cstdint>
#include <math.h>

#define EPS 1e-5f

// ---------------- scratch (device globals) ----------------
__device__ float g_bufA[67108864];               // GEMM1 H outputs (max 131072x512, fp32)
__device__ __half g_b16[16777216];               // GEMM2 fp16 outputs (max 32768x512)
__device__ __half g_f0h[33554432];               // f0 fp16
__device__ __half g_f1h[16777216];               // f1 fp16
__device__ __half g_f2h[8388608];                // f2 fp16
__device__ __half g_wh[4194304];                 // weight fp16 planes (all 8 GEMMs)
__device__ float g_sum[1024];
__device__ float g_sumsq[1024];
__device__ float g_scale[1024];
__device__ float g_shift[1024];

// ---------------- PTX helpers ----------------
__device__ __forceinline__ uint32_t smem_u32(const void* p) {
    uint32_t a;
    asm("{ .reg .u64 t; cvta.to.shared.u64 t, %1; cvt.u32.u64 %0, t; }" : "=r"(a) : "l"(p));
    return a;
}
__device__ __forceinline__ void cp16(uint32_t sdst, const void* gsrc) {
    asm volatile("cp.async.cg.shared.global [%0], [%1], 16;" :: "r"(sdst), "l"(gsrc));
}
#define CP_COMMIT() asm volatile("cp.async.commit_group;" ::: "memory")
#define CP_WAIT(n)  asm volatile("cp.async.wait_group %0;" :: "n"(n) : "memory")

__device__ __forceinline__ void ldsm_x4(uint32_t* r, uint32_t addr) {
    asm volatile("ldmatrix.sync.aligned.m8n8.x4.shared.b16 {%0,%1,%2,%3}, [%4];"
                 : "=r"(r[0]), "=r"(r[1]), "=r"(r[2]), "=r"(r[3]) : "r"(addr));
}
__device__ __forceinline__ void ldsm_x4_t(uint32_t* r, uint32_t addr) {
    asm volatile("ldmatrix.sync.aligned.m8n8.x4.trans.shared.b16 {%0,%1,%2,%3}, [%4];"
                 : "=r"(r[0]), "=r"(r[1]), "=r"(r[2]), "=r"(r[3]) : "r"(addr));
}
__device__ __forceinline__ void mma16816(float* d, const uint32_t* a, uint32_t b0, uint32_t b1) {
    asm volatile("mma.sync.aligned.m16n8k16.row.col.f32.f16.f16.f32 "
                 "{%0,%1,%2,%3}, {%4,%5,%6,%7}, {%8,%9}, {%0,%1,%2,%3};"
                 : "+f"(d[0]), "+f"(d[1]), "+f"(d[2]), "+f"(d[3])
                 : "r"(a[0]), "r"(a[1]), "r"(a[2]), "r"(a[3]), "r"(b0), "r"(b1));
}

// fp32x4 -> fp16x4 (8B)
__device__ __forceinline__ void cvt4h(float4 v, char* p) {
    __half2 h01 = __floats2half2_rn(v.x, v.y);
    __half2 h23 = __floats2half2_rn(v.z, v.w);
    uint2 u;
    u.x = *reinterpret_cast<uint32_t*>(&h01);
    u.y = *reinterpret_cast<uint32_t*>(&h23);
    *reinterpret_cast<uint2*>(p) = u;
}

// ---------------- elementwise kernels ----------------
__global__ void zero_stats_kernel(int n) {
    int i = blockIdx.x * blockDim.x + threadIdx.x;
    if (i < n) { g_sum[i] = 0.f; g_sumsq[i] = 0.f; }
}

__global__ void finalize_stats_kernel(const float* __restrict__ gamma,
                                      const float* __restrict__ beta,
                                      int N, float invM) {
    int i = blockIdx.x * blockDim.x + threadIdx.x;
    if (i >= N) return;
    float mu  = g_sum[i] * invM;
    float var = g_sumsq[i] * invM - mu * mu;
    float sc  = gamma[i] * rsqrtf(var + EPS);
    g_scale[i] = sc;
    g_shift[i] = beta[i] - mu * sc;
}

// fp32 -> fp16 plane, same layout (weights or activations)
__global__ void cvt_kernel(const float* __restrict__ W,
                           __half* __restrict__ hp, long long total4) {
    for (long long i = (long long)blockIdx.x * blockDim.x + threadIdx.x;
         i < total4; i += (long long)gridDim.x * blockDim.x) {
        float4 v = *(const float4*)(W + i * 4);
        cvt4h(v, (char*)(hp + i * 4));
    }
}

// ---------------- gemm16: GEMM1 kernel (fp16 A via cp.async) ----------------
// C = A @ W + bias, plus column stats.  A fp16 (M,K) [optionally CAT], W fp16 (K,N).
// BM=128, BN=128, BK=32; 256 threads (8 warps, 2x4), warp tile 64x32.
// 3-stage cp.async ring, prefetch distance 2.
template <bool CAT>
__global__ __launch_bounds__(256, 2)
void gemm16_kernel(const __half* __restrict__ Aleft, const __half* __restrict__ Aright,
                   const int* __restrict__ gidx, int outRPB, int srcRPB,
                   const __half* __restrict__ Wh,
                   const float* __restrict__ bias, float* __restrict__ C,
                   int M, int N, int K) {
    constexpr int A_STR = 80;                 // bytes per A smem row (32 fp16 + pad)
    constexpr int W_STR = 272;                // bytes per W smem row (128 fp16 + pad)
    constexpr int A_PLANE = 128 * A_STR;      // 10240
    constexpr int W_PLANE = 32 * W_STR;       // 8704
    constexpr int OFF_A = 0;
    constexpr int OFF_W = A_PLANE;
    constexpr int STAGE = A_PLANE + W_PLANE;  // 18944

    extern __shared__ char sm[];
    const uint32_t smb = smem_u32(sm);

    const int tid = threadIdx.x;
    const int wid = tid >> 5;
    const int lane = tid & 31;
    const int warp_m = (wid >> 2) * 64;
    const int warp_n = (wid & 3) * 32;
    const int bm0 = blockIdx.y * 128;
    const int bn0 = blockIdx.x * 128;
    const int T = K >> 5;
    const int Cl = K >> 1;                    // only used when CAT

    // A cp.async mapping: 512 x 16B chunks (128 rows x 4), 2 per thread
    int aKc[2];
    uint32_t aS[2];
    int offL[2], offR[2];
#pragma unroll
    for (int i = 0; i < 2; i++) {
        int c = tid + (i << 8);
        int arow = c >> 2;
        aKc[i] = (c & 3) * 8;                 // fp16 column within BK
        aS[i] = arow * A_STR + (c & 3) * 16;
        int r = bm0 + arow;
        if (CAT) {
            int b = r / outRPB;
            int src = b * srcRPB + gidx[r];
            offL[i] = r * Cl;
            offR[i] = src * Cl;
        } else {
            offL[i] = r * K;
            offR[i] = 0;
        }
    }
    // W cp.async mapping: 512 x 16B chunks, 2 per thread
    int wRow[2], wCol[2];
    uint32_t wS[2];
#pragma unroll
    for (int i = 0; i < 2; i++) {
        int c = tid + (i << 8);
        wRow[i] = c >> 4;
        wCol[i] = (c & 15) * 8;
        wS[i] = wRow[i] * W_STR + (c & 15) * 16;
    }

    // ldmatrix offsets (stage-relative)
    uint32_t a_off[4], b_off[2];
#pragma unroll
    for (int mt = 0; mt < 4; mt++)
        a_off[mt] = (uint32_t)((warp_m + mt * 16 + (lane & 15)) * A_STR + ((lane >> 4) << 3) * 2);
#pragma unroll
    for (int np = 0; np < 2; np++)
        b_off[np] = (uint32_t)((lane & 15) * W_STR + (warp_n + np * 16 + ((lane >> 4) << 3)) * 2);

    float acc[4][4][4];
#pragma unroll
    for (int mt = 0; mt < 4; mt++)
#pragma unroll
        for (int nt = 0; nt < 4; nt++)
#pragma unroll
            for (int q = 0; q < 4; q++) acc[mt][nt][q] = 0.f;

    // issue one stage's loads
    auto issue_stage = [&](int t, uint32_t sb) {
        const int k0 = t << 5;
#pragma unroll
        for (int i = 0; i < 2; i++) {
            int col = k0 + aKc[i];
            const __half* src;
            if (CAT)
                src = (col < Cl) ? (Aleft + offL[i] + col) : (Aright + offR[i] + (col - Cl));
            else
                src = Aleft + offL[i] + col;
            cp16(sb + OFF_A + aS[i], src);
        }
#pragma unroll
        for (int i = 0; i < 2; i++) {
            size_t gw = (size_t)(k0 + wRow[i]) * N + bn0 + wCol[i];
            cp16(sb + OFF_W + wS[i], Wh + gw);
        }
    };

    // prologue: stages 0 and 1
    issue_stage(0, smb);
    CP_COMMIT();
    if (1 < T) issue_stage(1, smb + STAGE);
    CP_COMMIT();

    int sread = 0, swrite = 2;
    for (int t = 0; t < T; t++) {
        __syncthreads();                      // all warps done reading ring slot swrite
        if (t + 2 < T) issue_stage(t + 2, smb + swrite * STAGE);
        CP_COMMIT();
        CP_WAIT(2);                           // stage t arrived
        __syncthreads();

        const uint32_t sbase = smb + sread * STAGE;
#pragma unroll
        for (int ks = 0; ks < 2; ks++) {
            uint32_t ah[4][4];
#pragma unroll
            for (int mt = 0; mt < 4; mt++)
                ldsm_x4(ah[mt], sbase + OFF_A + a_off[mt] + ks * 32);
#pragma unroll
            for (int np = 0; np < 2; np++) {
                uint32_t bh[4];
                ldsm_x4_t(bh, sbase + OFF_W + b_off[np] + ks * (16 * W_STR));
#pragma unroll
                for (int mt = 0; mt < 4; mt++)
#pragma unroll
                    for (int half = 0; half < 2; half++)
                        mma16816(acc[mt][np * 2 + half], ah[mt], bh[half * 2], bh[half * 2 + 1]);
            }
        }
        sread = (sread + 1 == 3) ? 0 : sread + 1;
        swrite = (swrite + 1 == 3) ? 0 : swrite + 1;
    }

    // ---- epilogue: bias + fp32 store + column stats ----
#pragma unroll
    for (int nt = 0; nt < 4; nt++) {
        int c0 = bn0 + warp_n + (nt >> 1) * 16 + (nt & 1) * 8 + (lane & 3) * 2;
        float b0 = bias[c0], b1 = bias[c0 + 1];
        float s0 = 0.f, s1 = 0.f, q0 = 0.f, q1 = 0.f;
#pragma unroll
        for (int mt = 0; mt < 4; mt++) {
            int r0 = bm0 + warp_m + mt * 16 + (lane >> 2);
            float v0 = acc[mt][nt][0] + b0, v1 = acc[mt][nt][1] + b1;
            float v2 = acc[mt][nt][2] + b0, v3 = acc[mt][nt][3] + b1;
            float2 p0; p0.x = v0; p0.y = v1;
            float2 p1; p1.x = v2; p1.y = v3;
            *(float2*)(C + (size_t)r0 * N + c0) = p0;
            *(float2*)(C + (size_t)(r0 + 8) * N + c0) = p1;
            s0 += v0 + v2; s1 += v1 + v3;
            q0 += v0 * v0 + v2 * v2; q1 += v1 * v1 + v3 * v3;
        }
#pragma unroll
        for (int off = 4; off < 32; off <<= 1) {
            s0 += __shfl_xor_sync(0xFFFFFFFFu, s0, off);
            s1 += __shfl_xor_sync(0xFFFFFFFFu, s1, off);
            q0 += __shfl_xor_sync(0xFFFFFFFFu, q0, off);
            q1 += __shfl_xor_sync(0xFFFFFFFFu, q1, off);
        }
        if ((lane >> 2) == 0) {
            atomicAdd(&g_sum[c0], s0);
            atomicAdd(&g_sum[c0 + 1], s1);
            atomicAdd(&g_sumsq[c0], q0);
            atomicAdd(&g_sumsq[c0 + 1], q1);
        }
    }
}

// ---------------- gemm32: GEMM2 kernel (fp32 A + BN normalize + ReLU) ----------------
// C = relu(A*scale+shift) @ W + bias.  Output fp16 (OUT16) or fp32.
template <bool OUT16>
__global__ __launch_bounds__(256, 2)
void gemm32_kernel(const float* __restrict__ A,
                   const __half* __restrict__ Wh,
                   const float* __restrict__ bias, void* __restrict__ Cout,
                   int M, int N, int K) {
    constexpr int A_STR = 80;
    constexpr int W_STR = 272;
    constexpr int A_PLANE = 128 * A_STR;
    constexpr int W_PLANE = 32 * W_STR;
    constexpr int OFF_A  = 0;
    constexpr int OFF_WH = A_PLANE;
    constexpr int STAGE = A_PLANE + W_PLANE;  // 18944

    extern __shared__ char sm[];
    const uint32_t smb = smem_u32(sm);

    const int tid = threadIdx.x;
    const int wid = tid >> 5;
    const int lane = tid & 31;
    const int warp_m = (wid >> 2) * 64;
    const int warp_n = (wid & 3) * 32;
    const int bm0 = blockIdx.y * 128;
    const int bn0 = blockIdx.x * 128;
    const int T = K >> 5;

    int a_row[4], a_c[4];
    uint32_t a_soff[4];
#pragma unroll
    for (int i = 0; i < 4; i++) {
        int idx = tid + (i << 8);
        a_row[i] = idx >> 3;
        a_c[i] = (idx & 7) << 2;
        a_soff[i] = a_row[i] * A_STR + a_c[i] * 2;
    }
    int wRow[2], wCol[2];
    uint32_t wS[2];
#pragma unroll
    for (int i = 0; i < 2; i++) {
        int c = tid + (i << 8);
        wRow[i] = c >> 4;
        wCol[i] = (c & 15) * 8;
        wS[i] = wRow[i] * W_STR + (c & 15) * 16;
    }

    uint32_t a_off[4], b_off[2];
#pragma unroll
    for (int mt = 0; mt < 4; mt++)
        a_off[mt] = (uint32_t)((warp_m + mt * 16 + (lane & 15)) * A_STR + ((lane >> 4) << 3) * 2);
#pragma unroll
    for (int np = 0; np < 2; np++)
        b_off[np] = (uint32_t)((lane & 15) * W_STR + (warp_n + np * 16 + ((lane >> 4) << 3)) * 2);

    float acc[4][4][4];
#pragma unroll
    for (int mt = 0; mt < 4; mt++)
#pragma unroll
        for (int nt = 0; nt < 4; nt++)
#pragma unroll
            for (int q = 0; q < 4; q++) acc[mt][nt][q] = 0.f;

    float4 ar[4];

    // prologue
    {
#pragma unroll
        for (int i = 0; i < 2; i++) {
            size_t gw = (size_t)wRow[i] * N + bn0 + wCol[i];
            cp16(smb + OFF_WH + wS[i], Wh + gw);
        }
        CP_COMMIT();
#pragma unroll
        for (int i = 0; i < 4; i++)
            ar[i] = *(const float4*)(A + (size_t)(bm0 + a_row[i]) * K + a_c[i]);
#pragma unroll
        for (int i = 0; i < 4; i++) {
            float4 v = ar[i];
            float4 sc = *(const float4*)(g_scale + a_c[i]);
            float4 sh = *(const float4*)(g_shift + a_c[i]);
            v.x = fmaxf(v.x * sc.x + sh.x, 0.f);
            v.y = fmaxf(v.y * sc.y + sh.y, 0.f);
            v.z = fmaxf(v.z * sc.z + sh.z, 0.f);
            v.w = fmaxf(v.w * sc.w + sh.w, 0.f);
            cvt4h(v, sm + OFF_A + a_soff[i]);
        }
        CP_WAIT(0);
    }
    __syncthreads();

    for (int t = 0; t < T; t++) {
        const int s = t & 1;
        const uint32_t sbase = smb + s * STAGE;
        const bool has_next = (t + 1 < T);
        const int k0n = (t + 1) << 5;

        if (has_next) {
            uint32_t nb = smb + (s ^ 1) * STAGE;
#pragma unroll
            for (int i = 0; i < 2; i++) {
                size_t gw = (size_t)(k0n + wRow[i]) * N + bn0 + wCol[i];
                cp16(nb + OFF_WH + wS[i], Wh + gw);
            }
            CP_COMMIT();
#pragma unroll
            for (int i = 0; i < 4; i++)
                ar[i] = *(const float4*)(A + (size_t)(bm0 + a_row[i]) * K + k0n + a_c[i]);
        }

#pragma unroll
        for (int ks = 0; ks < 2; ks++) {
            uint32_t ah[4][4];
#pragma unroll
            for (int mt = 0; mt < 4; mt++)
                ldsm_x4(ah[mt], sbase + OFF_A + a_off[mt] + ks * 32);
#pragma unroll
            for (int np = 0; np < 2; np++) {
                uint32_t bh[4];
                ldsm_x4_t(bh, sbase + OFF_WH + b_off[np] + ks * (16 * W_STR));
#pragma unroll
                for (int mt = 0; mt < 4; mt++)
#pragma unroll
                    for (int half = 0; half < 2; half++)
                        mma16816(acc[mt][np * 2 + half], ah[mt], bh[half * 2], bh[half * 2 + 1]);
            }
        }

        if (has_next) {
            char* nb = sm + (s ^ 1) * STAGE;
#pragma unroll
            for (int i = 0; i < 4; i++) {
                float4 v = ar[i];
                float4 sc = *(const float4*)(g_scale + k0n + a_c[i]);
                float4 sh = *(const float4*)(g_shift + k0n + a_c[i]);
                v.x = fmaxf(v.x * sc.x + sh.x, 0.f);
                v.y = fmaxf(v.y * sc.y + sh.y, 0.f);
                v.z = fmaxf(v.z * sc.z + sh.z, 0.f);
                v.w = fmaxf(v.w * sc.w + sh.w, 0.f);
                cvt4h(v, nb + OFF_A + a_soff[i]);
            }
            CP_WAIT(0);
        }
        __syncthreads();
    }

    // epilogue
#pragma unroll
    for (int nt = 0; nt < 4; nt++) {
        int c0 = bn0 + warp_n + (nt >> 1) * 16 + (nt & 1) * 8 + (lane & 3) * 2;
        float b0 = bias[c0], b1 = bias[c0 + 1];
#pragma unroll
        for (int mt = 0; mt < 4; mt++) {
            int r0 = bm0 + warp_m + mt * 16 + (lane >> 2);
            float v0 = acc[mt][nt][0] + b0, v1 = acc[mt][nt][1] + b1;
            float v2 = acc[mt][nt][2] + b0, v3 = acc[mt][nt][3] + b1;
            if (OUT16) {
                __half* C16 = (__half*)Cout;
                __half2 h0 = __floats2half2_rn(v0, v1);
                __half2 h1 = __floats2half2_rn(v2, v3);
                *(__half2*)(C16 + (size_t)r0 * N + c0) = h0;
                *(__half2*)(C16 + (size_t)(r0 + 8) * N + c0) = h1;
            } else {
                float* C = (float*)Cout;
                float2 p0; p0.x = v0; p0.y = v1;
                float2 p1; p1.x = v2; p1.y = v3;
                *(float2*)(C + (size_t)r0 * N + c0) = p0;
                *(float2*)(C + (size_t)(r0 + 8) * N + c0) = p1;
            }
        }
    }
}

// ---------------- host orchestration ----------------
static const int G16_SMEM = 3 * 18944;   // 56832
static const int G32_SMEM = 2 * 18944;   // 37888

static __half *s_wh, *s_b16, *s_f0h, *s_f1h, *s_f2h;
static float *s_bufA;

template <bool CAT>
static void run_g16(const __half* left, const __half* right, const int* gidx,
                    int outRPB, int srcRPB, size_t woff,
                    const float* bias, float* C, int M, int N, int K) {
    dim3 grid(N / 128, M / 128);
    gemm16_kernel<CAT><<<grid, 256, G16_SMEM>>>(left, right, gidx, outRPB, srcRPB,
                                                s_wh + woff, bias, C, M, N, K);
}

template <bool OUT16>
static void run_g32(const float* A, size_t woff, const float* bias, void* C,
                    int M, int N, int K) {
    dim3 grid(N / 128, M / 128);
    gemm32_kernel<OUT16><<<grid, 256, G32_SMEM>>>(A, s_wh + woff, bias, C, M, N, K);
}

extern "C" void kernel_launch(void* const* d_in, const int* in_sizes, int n_in,
                              void* d_out, int out_size) {
    const float* f0 = (const float*)d_in[0];
    const float* f1 = (const float*)d_in[1];
    const float* f2 = (const float*)d_in[2];
    const float* up0_w1 = (const float*)d_in[3];
    const float* up0_b1 = (const float*)d_in[4];
    const float* up0_g  = (const float*)d_in[5];
    const float* up0_be = (const float*)d_in[6];
    const float* up0_w2 = (const float*)d_in[7];
    const float* up0_b2 = (const float*)d_in[8];
    const float* up1_w1 = (const float*)d_in[9];
    const float* up1_b1 = (const float*)d_in[10];
    const float* up1_g  = (const float*)d_in[11];
    const float* up1_be = (const float*)d_in[12];
    const float* up1_w2 = (const float*)d_in[13];
    const float* up1_b2 = (const float*)d_in[14];
    const float* skip0_w1 = (const float*)d_in[15];
    const float* skip0_b1 = (const float*)d_in[16];
    const float* skip0_g  = (const float*)d_in[17];
    const float* skip0_be = (const float*)d_in[18];
    const float* skip0_w2 = (const float*)d_in[19];
    const float* skip0_b2 = (const float*)d_in[20];
    const float* skip1_w1 = (const float*)d_in[21];
    const float* skip1_b1 = (const float*)d_in[22];
    const float* skip1_g  = (const float*)d_in[23];
    const float* skip1_be = (const float*)d_in[24];
    const float* skip1_w2 = (const float*)d_in[25];
    const float* skip1_b2 = (const float*)d_in[26];
    const int*   pool0 = (const int*)d_in[27];
    const int*   pool1 = (const int*)d_in[28];
    float* out = (float*)d_out;

    cudaGetSymbolAddress((void**)&s_bufA, g_bufA);
    cudaGetSymbolAddress((void**)&s_b16, g_b16);
    cudaGetSymbolAddress((void**)&s_f0h, g_f0h);
    cudaGetSymbolAddress((void**)&s_f1h, g_f1h);
    cudaGetSymbolAddress((void**)&s_f2h, g_f2h);
    cudaGetSymbolAddress((void**)&s_wh, g_wh);

    cudaFuncSetAttribute(gemm16_kernel<false>, cudaFuncAttributeMaxDynamicSharedMemorySize, G16_SMEM);
    cudaFuncSetAttribute(gemm16_kernel<true>,  cudaFuncAttributeMaxDynamicSharedMemorySize, G16_SMEM);
    cudaFuncSetAttribute(gemm32_kernel<false>, cudaFuncAttributeMaxDynamicSharedMemorySize, G32_SMEM);
    cudaFuncSetAttribute(gemm32_kernel<true>,  cudaFuncAttributeMaxDynamicSharedMemorySize, G32_SMEM);

    const int B = 4;
    const int N0 = 32768, N1 = 8192, N2 = 2048;
    const int C0 = 256, C1 = 512, C2 = 1024;
    const int M_u1 = B * N2, M_s1 = B * N1, M_s0 = B * N0;

    // weight plane offsets (K,N) layout
    const size_t O_U1W1 = 0;
    const size_t O_U1W2 = 1048576;
    const size_t O_S1W1 = 1572864;
    const size_t O_S1W2 = 2621440;
    const size_t O_U0W1 = 3145728;
    const size_t O_U0W2 = 3407872;
    const size_t O_S0W1 = 3538944;
    const size_t O_S0W2 = 3801088;

    // ---- pre-convert activations to fp16 ----
    cvt_kernel<<<512, 256>>>(f2, s_f2h, (long long)M_u1 * C2 / 4);
    cvt_kernel<<<512, 256>>>(f1, s_f1h, (long long)M_s1 * C1 / 4);
    cvt_kernel<<<1024, 256>>>(f0, s_f0h, (long long)M_s0 * C0 / 4);

    // ---- up1 MLP: f2h (8192,1024) -> 1024 -> 512 ----
    zero_stats_kernel<<<4, 256>>>(1024);
    cvt_kernel<<<512, 256>>>(up1_w1, s_wh + O_U1W1, (long long)C2 * C2 / 4);
    cvt_kernel<<<512, 256>>>(up1_w2, s_wh + O_U1W2, (long long)C2 * C1 / 4);
    run_g16<false>(s_f2h, nullptr, nullptr, 1, 1, O_U1W1, up1_b1, s_bufA, M_u1, C2, C2);
    finalize_stats_kernel<<<4, 256>>>(up1_g, up1_be, C2, 1.0f / M_u1);
    run_g32<true>(s_bufA, O_U1W2, up1_b2, s_b16, M_u1, C1, C2);

    // ---- skip1 MLP: concat(f1h, gather(b16, pool1)) (32768,1024) -> 1024 -> 512 ----
    zero_stats_kernel<<<4, 256>>>(1024);
    cvt_kernel<<<512, 256>>>(skip1_w1, s_wh + O_S1W1, (long long)(2 * C1) * (2 * C1) / 4);
    cvt_kernel<<<512, 256>>>(skip1_w2, s_wh + O_S1W2, (long long)(2 * C1) * C1 / 4);
    run_g16<true>(s_f1h, s_b16, pool1, N1, N2, O_S1W1, skip1_b1, s_bufA, M_s1, 2 * C1, 2 * C1);
    finalize_stats_kernel<<<4, 256>>>(skip1_g, skip1_be, 2 * C1, 1.0f / M_s1);
    run_g32<true>(s_bufA, O_S1W2, skip1_b2, s_b16, M_s1, C1, 2 * C1);

    // ---- up0 MLP: b16 (32768,512) -> 512 -> 256 ----
    zero_stats_kernel<<<2, 256>>>(512);
    cvt_kernel<<<256, 256>>>(up0_w1, s_wh + O_U0W1, (long long)C1 * C1 / 4);
    cvt_kernel<<<256, 256>>>(up0_w2, s_wh + O_U0W2, (long long)C1 * C0 / 4);
    run_g16<false>(s_b16, nullptr, nullptr, 1, 1, O_U0W1, up0_b1, s_bufA, M_s1, C1, C1);
    finalize_stats_kernel<<<2, 256>>>(up0_g, up0_be, C1, 1.0f / M_s1);
    run_g32<true>(s_bufA, O_U0W2, up0_b2, s_b16, M_s1, C0, C1);

    // ---- skip0 MLP: concat(f0h, gather(b16, pool0)) (131072,512) -> 512 -> 256 -> out ----
    zero_stats_kernel<<<2, 256>>>(512);
    cvt_kernel<<<256, 256>>>(skip0_w1, s_wh + O_S0W1, (long long)(2 * C0) * (2 * C0) / 4);
    cvt_kernel<<<256, 256>>>(skip0_w2, s_wh + O_S0W2, (long long)(2 * C0) * C0 / 4);
    run_g16<true>(s_f0h, s_b16, pool0, N0, N1, O_S0W1, skip0_b1, s_bufA, M_s0, 2 * C0, 2 * C0);
    finalize_stats_kernel<<<2, 256>>>(skip0_g, skip0_be, 2 * C0, 1.0f / M_s0);
    run_g32<false>(s_bufA, O_S0W2, skip0_b2, out, M_s0, C0, 2 * C0);
}

// round 15
// speedup vs baseline: 2.2929x; 1.0312x over previous
#include <cuda_runtime.h>
#include <cuda_fp16.h>
#include <cstdint>
#include <math.h>

#define EPS 1e-5f

// ---------------- scratch (device globals) ----------------
__device__ float g_bufA[67108864];               // GEMM1 H outputs (max 131072x512, fp32)
__device__ __half g_b16[16777216];               // GEMM2 fp16 outputs (max 32768x512)
__device__ __half g_f0h[33554432];               // f0 fp16
__device__ __half g_f1h[16777216];               // f1 fp16
__device__ __half g_f2h[8388608];                // f2 fp16
__device__ __half g_wh[4194304];                 // weight fp16 planes (all 8 GEMMs)
__device__ float g_sum[1024];
__device__ float g_sumsq[1024];
__device__ float g_scale[1024];
__device__ float g_shift[1024];

// ---------------- PTX helpers ----------------
__device__ __forceinline__ uint32_t smem_u32(const void* p) {
    uint32_t a;
    asm("{ .reg .u64 t; cvta.to.shared.u64 t, %1; cvt.u32.u64 %0, t; }" : "=r"(a) : "l"(p));
    return a;
}
__device__ __forceinline__ void cp16(uint32_t sdst, const void* gsrc) {
    asm volatile("cp.async.cg.shared.global [%0], [%1], 16;" :: "r"(sdst), "l"(gsrc));
}
#define CP_COMMIT() asm volatile("cp.async.commit_group;" ::: "memory")
#define CP_WAIT(n)  asm volatile("cp.async.wait_group %0;" :: "n"(n) : "memory")

__device__ __forceinline__ void ldsm_x4(uint32_t* r, uint32_t addr) {
    asm volatile("ldmatrix.sync.aligned.m8n8.x4.shared.b16 {%0,%1,%2,%3}, [%4];"
                 : "=r"(r[0]), "=r"(r[1]), "=r"(r[2]), "=r"(r[3]) : "r"(addr));
}
__device__ __forceinline__ void ldsm_x4_t(uint32_t* r, uint32_t addr) {
    asm volatile("ldmatrix.sync.aligned.m8n8.x4.trans.shared.b16 {%0,%1,%2,%3}, [%4];"
                 : "=r"(r[0]), "=r"(r[1]), "=r"(r[2]), "=r"(r[3]) : "r"(addr));
}
__device__ __forceinline__ void mma16816(float* d, const uint32_t* a, uint32_t b0, uint32_t b1) {
    asm volatile("mma.sync.aligned.m16n8k16.row.col.f32.f16.f16.f32 "
                 "{%0,%1,%2,%3}, {%4,%5,%6,%7}, {%8,%9}, {%0,%1,%2,%3};"
                 : "+f"(d[0]), "+f"(d[1]), "+f"(d[2]), "+f"(d[3])
                 : "r"(a[0]), "r"(a[1]), "r"(a[2]), "r"(a[3]), "r"(b0), "r"(b1));
}

// fp32x4 -> fp16x4 (8B)
__device__ __forceinline__ void cvt4h(float4 v, char* p) {
    __half2 h01 = __floats2half2_rn(v.x, v.y);
    __half2 h23 = __floats2half2_rn(v.z, v.w);
    uint2 u;
    u.x = *reinterpret_cast<uint32_t*>(&h01);
    u.y = *reinterpret_cast<uint32_t*>(&h23);
    *reinterpret_cast<uint2*>(p) = u;
}

// ---------------- elementwise kernels ----------------
__global__ void zero_stats_kernel(int n) {
    int i = blockIdx.x * blockDim.x + threadIdx.x;
    if (i < n) { g_sum[i] = 0.f; g_sumsq[i] = 0.f; }
}

__global__ void finalize_stats_kernel(const float* __restrict__ gamma,
                                      const float* __restrict__ beta,
                                      int N, float invM) {
    int i = blockIdx.x * blockDim.x + threadIdx.x;
    if (i >= N) return;
    float mu  = g_sum[i] * invM;
    float var = g_sumsq[i] * invM - mu * mu;
    float sc  = gamma[i] * rsqrtf(var + EPS);
    g_scale[i] = sc;
    g_shift[i] = beta[i] - mu * sc;
}

// fp32 -> fp16 plane, same layout (weights or activations)
__global__ void cvt_kernel(const float* __restrict__ W,
                           __half* __restrict__ hp, long long total4) {
    for (long long i = (long long)blockIdx.x * blockDim.x + threadIdx.x;
         i < total4; i += (long long)gridDim.x * blockDim.x) {
        float4 v = *(const float4*)(W + i * 4);
        cvt4h(v, (char*)(hp + i * 4));
    }
}

// ---------------- gemm16: GEMM1 kernel (fp16 A, 4-stage single-sync pipeline) ----------------
// C = A @ W + bias, plus column stats.  A fp16 (M,K) [optionally CAT], W fp16 (K,N).
// BM=128, BN=128, BK=32; 256 threads (8 warps, 2x4), warp tile 64x32.
template <bool CAT>
__global__ __launch_bounds__(256, 2)
void gemm16_kernel(const __half* __restrict__ Aleft, const __half* __restrict__ Aright,
                   const int* __restrict__ gidx, int outRPB, int srcRPB,
                   const __half* __restrict__ Wh,
                   const float* __restrict__ bias, float* __restrict__ C,
                   int M, int N, int K) {
    constexpr int A_STR = 80;
    constexpr int W_STR = 272;
    constexpr int A_PLANE = 128 * A_STR;      // 10240
    constexpr int W_PLANE = 32 * W_STR;       // 8704
    constexpr int OFF_A = 0;
    constexpr int OFF_W = A_PLANE;
    constexpr int STAGE = A_PLANE + W_PLANE;  // 18944
    constexpr int S = 4;

    extern __shared__ char sm[];
    const uint32_t smb = smem_u32(sm);

    const int tid = threadIdx.x;
    const int wid = tid >> 5;
    const int lane = tid & 31;
    const int warp_m = (wid >> 2) * 64;
    const int warp_n = (wid & 3) * 32;
    const int bm0 = blockIdx.y * 128;
    const int bn0 = blockIdx.x * 128;
    const int T = K >> 5;
    const int Cl = K >> 1;

    // A cp.async mapping: 512 x 16B chunks, 2 per thread
    int aKc[2];
    uint32_t aS[2];
    int offL[2], offR[2];
#pragma unroll
    for (int i = 0; i < 2; i++) {
        int c = tid + (i << 8);
        int arow = c >> 2;
        aKc[i] = (c & 3) * 8;
        aS[i] = arow * A_STR + (c & 3) * 16;
        int r = bm0 + arow;
        if (CAT) {
            int b = r / outRPB;
            int src = b * srcRPB + gidx[r];
            offL[i] = r * Cl;
            offR[i] = src * Cl;
        } else {
            offL[i] = r * K;
            offR[i] = 0;
        }
    }
    // W cp.async mapping: 512 x 16B chunks, 2 per thread
    int wRow[2], wCol[2];
    uint32_t wS[2];
#pragma unroll
    for (int i = 0; i < 2; i++) {
        int c = tid + (i << 8);
        wRow[i] = c >> 4;
        wCol[i] = (c & 15) * 8;
        wS[i] = wRow[i] * W_STR + (c & 15) * 16;
    }

    uint32_t a_off[4], b_off[2];
#pragma unroll
    for (int mt = 0; mt < 4; mt++)
        a_off[mt] = (uint32_t)((warp_m + mt * 16 + (lane & 15)) * A_STR + ((lane >> 4) << 3) * 2);
#pragma unroll
    for (int np = 0; np < 2; np++)
        b_off[np] = (uint32_t)((lane & 15) * W_STR + (warp_n + np * 16 + ((lane >> 4) << 3)) * 2);

    float acc[4][4][4];
#pragma unroll
    for (int mt = 0; mt < 4; mt++)
#pragma unroll
        for (int nt = 0; nt < 4; nt++)
#pragma unroll
            for (int q = 0; q < 4; q++) acc[mt][nt][q] = 0.f;

    auto issue_stage = [&](int t, uint32_t sb) {
        const int k0 = t << 5;
#pragma unroll
        for (int i = 0; i < 2; i++) {
            int col = k0 + aKc[i];
            const __half* src;
            if (CAT)
                src = (col < Cl) ? (Aleft + offL[i] + col) : (Aright + offR[i] + (col - Cl));
            else
                src = Aleft + offL[i] + col;
            cp16(sb + OFF_A + aS[i], src);
        }
#pragma unroll
        for (int i = 0; i < 2; i++) {
            size_t gw = (size_t)(k0 + wRow[i]) * N + bn0 + wCol[i];
            cp16(sb + OFF_W + wS[i], Wh + gw);
        }
    };

    // prologue: issue stages 0..2
#pragma unroll
    for (int p = 0; p < S - 1; p++) {
        if (p < T) issue_stage(p, smb + p * STAGE);
        CP_COMMIT();
    }

    for (int t = 0; t < T; t++) {
        CP_WAIT(2);                            // stage t landed
        __syncthreads();                       // single barrier per K-step
        if (t + S - 1 < T) issue_stage(t + S - 1, smb + ((t + S - 1) & (S - 1)) * STAGE);
        CP_COMMIT();

        const uint32_t sbase = smb + (t & (S - 1)) * STAGE;
#pragma unroll
        for (int ks = 0; ks < 2; ks++) {
            uint32_t ah[4][4];
#pragma unroll
            for (int mt = 0; mt < 4; mt++)
                ldsm_x4(ah[mt], sbase + OFF_A + a_off[mt] + ks * 32);
#pragma unroll
            for (int np = 0; np < 2; np++) {
                uint32_t bh[4];
                ldsm_x4_t(bh, sbase + OFF_W + b_off[np] + ks * (16 * W_STR));
#pragma unroll
                for (int mt = 0; mt < 4; mt++)
#pragma unroll
                    for (int half = 0; half < 2; half++)
                        mma16816(acc[mt][np * 2 + half], ah[mt], bh[half * 2], bh[half * 2 + 1]);
            }
        }
    }

    // ---- epilogue: bias + fp32 store + column stats ----
#pragma unroll
    for (int nt = 0; nt < 4; nt++) {
        int c0 = bn0 + warp_n + (nt >> 1) * 16 + (nt & 1) * 8 + (lane & 3) * 2;
        float b0 = bias[c0], b1 = bias[c0 + 1];
        float s0 = 0.f, s1 = 0.f, q0 = 0.f, q1 = 0.f;
#pragma unroll
        for (int mt = 0; mt < 4; mt++) {
            int r0 = bm0 + warp_m + mt * 16 + (lane >> 2);
            float v0 = acc[mt][nt][0] + b0, v1 = acc[mt][nt][1] + b1;
            float v2 = acc[mt][nt][2] + b0, v3 = acc[mt][nt][3] + b1;
            float2 p0; p0.x = v0; p0.y = v1;
            float2 p1; p1.x = v2; p1.y = v3;
            *(float2*)(C + (size_t)r0 * N + c0) = p0;
            *(float2*)(C + (size_t)(r0 + 8) * N + c0) = p1;
            s0 += v0 + v2; s1 += v1 + v3;
            q0 += v0 * v0 + v2 * v2; q1 += v1 * v1 + v3 * v3;
        }
#pragma unroll
        for (int off = 4; off < 32; off <<= 1) {
            s0 += __shfl_xor_sync(0xFFFFFFFFu, s0, off);
            s1 += __shfl_xor_sync(0xFFFFFFFFu, s1, off);
            q0 += __shfl_xor_sync(0xFFFFFFFFu, q0, off);
            q1 += __shfl_xor_sync(0xFFFFFFFFu, q1, off);
        }
        if ((lane >> 2) == 0) {
            atomicAdd(&g_sum[c0], s0);
            atomicAdd(&g_sum[c0 + 1], s1);
            atomicAdd(&g_sumsq[c0], q0);
            atomicAdd(&g_sumsq[c0 + 1], q1);
        }
    }
}

// ---------------- gemm32: GEMM2 kernel (fp32 A + BN normalize + ReLU) ----------------
template <bool OUT16>
__global__ __launch_bounds__(256, 2)
void gemm32_kernel(const float* __restrict__ A,
                   const __half* __restrict__ Wh,
                   const float* __restrict__ bias, void* __restrict__ Cout,
                   int M, int N, int K) {
    constexpr int A_STR = 80;
    constexpr int W_STR = 272;
    constexpr int A_PLANE = 128 * A_STR;
    constexpr int W_PLANE = 32 * W_STR;
    constexpr int OFF_A  = 0;
    constexpr int OFF_WH = A_PLANE;
    constexpr int STAGE = A_PLANE + W_PLANE;

    extern __shared__ char sm[];
    const uint32_t smb = smem_u32(sm);

    const int tid = threadIdx.x;
    const int wid = tid >> 5;
    const int lane = tid & 31;
    const int warp_m = (wid >> 2) * 64;
    const int warp_n = (wid & 3) * 32;
    const int bm0 = blockIdx.y * 128;
    const int bn0 = blockIdx.x * 128;
    const int T = K >> 5;

    int a_row[4], a_c[4];
    uint32_t a_soff[4];
#pragma unroll
    for (int i = 0; i < 4; i++) {
        int idx = tid + (i << 8);
        a_row[i] = idx >> 3;
        a_c[i] = (idx & 7) << 2;
        a_soff[i] = a_row[i] * A_STR + a_c[i] * 2;
    }
    int wRow[2], wCol[2];
    uint32_t wS[2];
#pragma unroll
    for (int i = 0; i < 2; i++) {
        int c = tid + (i << 8);
        wRow[i] = c >> 4;
        wCol[i] = (c & 15) * 8;
        wS[i] = wRow[i] * W_STR + (c & 15) * 16;
    }

    uint32_t a_off[4], b_off[2];
#pragma unroll
    for (int mt = 0; mt < 4; mt++)
        a_off[mt] = (uint32_t)((warp_m + mt * 16 + (lane & 15)) * A_STR + ((lane >> 4) << 3) * 2);
#pragma unroll
    for (int np = 0; np < 2; np++)
        b_off[np] = (uint32_t)((lane & 15) * W_STR + (warp_n + np * 16 + ((lane >> 4) << 3)) * 2);

    float acc[4][4][4];
#pragma unroll
    for (int mt = 0; mt < 4; mt++)
#pragma unroll
        for (int nt = 0; nt < 4; nt++)
#pragma unroll
            for (int q = 0; q < 4; q++) acc[mt][nt][q] = 0.f;

    float4 ar[4];

    {
#pragma unroll
        for (int i = 0; i < 2; i++) {
            size_t gw = (size_t)wRow[i] * N + bn0 + wCol[i];
            cp16(smb + OFF_WH + wS[i], Wh + gw);
        }
        CP_COMMIT();
#pragma unroll
        for (int i = 0; i < 4; i++)
            ar[i] = *(const float4*)(A + (size_t)(bm0 + a_row[i]) * K + a_c[i]);
#pragma unroll
        for (int i = 0; i < 4; i++) {
            float4 v = ar[i];
            float4 sc = *(const float4*)(g_scale + a_c[i]);
            float4 sh = *(const float4*)(g_shift + a_c[i]);
            v.x = fmaxf(v.x * sc.x + sh.x, 0.f);
            v.y = fmaxf(v.y * sc.y + sh.y, 0.f);
            v.z = fmaxf(v.z * sc.z + sh.z, 0.f);
            v.w = fmaxf(v.w * sc.w + sh.w, 0.f);
            cvt4h(v, sm + OFF_A + a_soff[i]);
        }
        CP_WAIT(0);
    }
    __syncthreads();

    for (int t = 0; t < T; t++) {
        const int s = t & 1;
        const uint32_t sbase = smb + s * STAGE;
        const bool has_next = (t + 1 < T);
        const int k0n = (t + 1) << 5;

        if (has_next) {
            uint32_t nb = smb + (s ^ 1) * STAGE;
#pragma unroll
            for (int i = 0; i < 2; i++) {
                size_t gw = (size_t)(k0n + wRow[i]) * N + bn0 + wCol[i];
                cp16(nb + OFF_WH + wS[i], Wh + gw);
            }
            CP_COMMIT();
#pragma unroll
            for (int i = 0; i < 4; i++)
                ar[i] = *(const float4*)(A + (size_t)(bm0 + a_row[i]) * K + k0n + a_c[i]);
        }

#pragma unroll
        for (int ks = 0; ks < 2; ks++) {
            uint32_t ah[4][4];
#pragma unroll
            for (int mt = 0; mt < 4; mt++)
                ldsm_x4(ah[mt], sbase + OFF_A + a_off[mt] + ks * 32);
#pragma unroll
            for (int np = 0; np < 2; np++) {
                uint32_t bh[4];
                ldsm_x4_t(bh, sbase + OFF_WH + b_off[np] + ks * (16 * W_STR));
#pragma unroll
                for (int mt = 0; mt < 4; mt++)
#pragma unroll
                    for (int half = 0; half < 2; half++)
                        mma16816(acc[mt][np * 2 + half], ah[mt], bh[half * 2], bh[half * 2 + 1]);
            }
        }

        if (has_next) {
            char* nb = sm + (s ^ 1) * STAGE;
#pragma unroll
            for (int i = 0; i < 4; i++) {
                float4 v = ar[i];
                float4 sc = *(const float4*)(g_scale + k0n + a_c[i]);
                float4 sh = *(const float4*)(g_shift + k0n + a_c[i]);
                v.x = fmaxf(v.x * sc.x + sh.x, 0.f);
                v.y = fmaxf(v.y * sc.y + sh.y, 0.f);
                v.z = fmaxf(v.z * sc.z + sh.z, 0.f);
                v.w = fmaxf(v.w * sc.w + sh.w, 0.f);
                cvt4h(v, nb + OFF_A + a_soff[i]);
            }
            CP_WAIT(0);
        }
        __syncthreads();
    }

#pragma unroll
    for (int nt = 0; nt < 4; nt++) {
        int c0 = bn0 + warp_n + (nt >> 1) * 16 + (nt & 1) * 8 + (lane & 3) * 2;
        float b0 = bias[c0], b1 = bias[c0 + 1];
#pragma unroll
        for (int mt = 0; mt < 4; mt++) {
            int r0 = bm0 + warp_m + mt * 16 + (lane >> 2);
            float v0 = acc[mt][nt][0] + b0, v1 = acc[mt][nt][1] + b1;
            float v2 = acc[mt][nt][2] + b0, v3 = acc[mt][nt][3] + b1;
            if (OUT16) {
                __half* C16 = (__half*)Cout;
                __half2 h0 = __floats2half2_rn(v0, v1);
                __half2 h1 = __floats2half2_rn(v2, v3);
                *(__half2*)(C16 + (size_t)r0 * N + c0) = h0;
                *(__half2*)(C16 + (size_t)(r0 + 8) * N + c0) = h1;
            } else {
                float* C = (float*)Cout;
                float2 p0; p0.x = v0; p0.y = v1;
                float2 p1; p1.x = v2; p1.y = v3;
                *(float2*)(C + (size_t)r0 * N + c0) = p0;
                *(float2*)(C + (size_t)(r0 + 8) * N + c0) = p1;
            }
        }
    }
}

// ---------------- host orchestration ----------------
static const int G16_SMEM = 4 * 18944;   // 75776
static const int G32_SMEM = 2 * 18944;   // 37888

static __half *s_wh, *s_b16, *s_f0h, *s_f1h, *s_f2h;
static float *s_bufA;

template <bool CAT>
static void run_g16(const __half* left, const __half* right, const int* gidx,
                    int outRPB, int srcRPB, size_t woff,
                    const float* bias, float* C, int M, int N, int K) {
    dim3 grid(N / 128, M / 128);
    gemm16_kernel<CAT><<<grid, 256, G16_SMEM>>>(left, right, gidx, outRPB, srcRPB,
                                                s_wh + woff, bias, C, M, N, K);
}

template <bool OUT16>
static void run_g32(const float* A, size_t woff, const float* bias, void* C,
                    int M, int N, int K) {
    dim3 grid(N / 128, M / 128);
    gemm32_kernel<OUT16><<<grid, 256, G32_SMEM>>>(A, s_wh + woff, bias, C, M, N, K);
}

extern "C" void kernel_launch(void* const* d_in, const int* in_sizes, int n_in,
                              void* d_out, int out_size) {
    const float* f0 = (const float*)d_in[0];
    const float* f1 = (const float*)d_in[1];
    const float* f2 = (const float*)d_in[2];
    const float* up0_w1 = (const float*)d_in[3];
    const float* up0_b1 = (const float*)d_in[4];
    const float* up0_g  = (const float*)d_in[5];
    const float* up0_be = (const float*)d_in[6];
    const float* up0_w2 = (const float*)d_in[7];
    const float* up0_b2 = (const float*)d_in[8];
    const float* up1_w1 = (const float*)d_in[9];
    const float* up1_b1 = (const float*)d_in[10];
    const float* up1_g  = (const float*)d_in[11];
    const float* up1_be = (const float*)d_in[12];
    const float* up1_w2 = (const float*)d_in[13];
    const float* up1_b2 = (const float*)d_in[14];
    const float* skip0_w1 = (const float*)d_in[15];
    const float* skip0_b1 = (const float*)d_in[16];
    const float* skip0_g  = (const float*)d_in[17];
    const float* skip0_be = (const float*)d_in[18];
    const float* skip0_w2 = (const float*)d_in[19];
    const float* skip0_b2 = (const float*)d_in[20];
    const float* skip1_w1 = (const float*)d_in[21];
    const float* skip1_b1 = (const float*)d_in[22];
    const float* skip1_g  = (const float*)d_in[23];
    const float* skip1_be = (const float*)d_in[24];
    const float* skip1_w2 = (const float*)d_in[25];
    const float* skip1_b2 = (const float*)d_in[26];
    const int*   pool0 = (const int*)d_in[27];
    const int*   pool1 = (const int*)d_in[28];
    float* out = (float*)d_out;

    cudaGetSymbolAddress((void**)&s_bufA, g_bufA);
    cudaGetSymbolAddress((void**)&s_b16, g_b16);
    cudaGetSymbolAddress((void**)&s_f0h, g_f0h);
    cudaGetSymbolAddress((void**)&s_f1h, g_f1h);
    cudaGetSymbolAddress((void**)&s_f2h, g_f2h);
    cudaGetSymbolAddress((void**)&s_wh, g_wh);

    cudaFuncSetAttribute(gemm16_kernel<false>, cudaFuncAttributeMaxDynamicSharedMemorySize, G16_SMEM);
    cudaFuncSetAttribute(gemm16_kernel<true>,  cudaFuncAttributeMaxDynamicSharedMemorySize, G16_SMEM);
    cudaFuncSetAttribute(gemm32_kernel<false>, cudaFuncAttributeMaxDynamicSharedMemorySize, G32_SMEM);
    cudaFuncSetAttribute(gemm32_kernel<true>,  cudaFuncAttributeMaxDynamicSharedMemorySize, G32_SMEM);

    const int B = 4;
    const int N0 = 32768, N1 = 8192, N2 = 2048;
    const int C0 = 256, C1 = 512, C2 = 1024;
    const int M_u1 = B * N2, M_s1 = B * N1, M_s0 = B * N0;

    const size_t O_U1W1 = 0;
    const size_t O_U1W2 = 1048576;
    const size_t O_S1W1 = 1572864;
    const size_t O_S1W2 = 2621440;
    const size_t O_U0W1 = 3145728;
    const size_t O_U0W2 = 3407872;
    const size_t O_S0W1 = 3538944;
    const size_t O_S0W2 = 3801088;

    // ---- up1 MLP: f2h (8192,1024) -> 1024 -> 512 ----
    cvt_kernel<<<512, 256>>>(f2, s_f2h, (long long)M_u1 * C2 / 4);                 // 0
    cvt_kernel<<<512, 256>>>(up1_w1, s_wh + O_U1W1, (long long)C2 * C2 / 4);       // 1
    zero_stats_kernel<<<4, 256>>>(1024);                                           // 2
    run_g16<false>(s_f2h, nullptr, nullptr, 1, 1, O_U1W1, up1_b1, s_bufA, M_u1, C2, C2);  // 3 <- profiled
    cvt_kernel<<<512, 256>>>(up1_w2, s_wh + O_U1W2, (long long)C2 * C1 / 4);
    finalize_stats_kernel<<<4, 256>>>(up1_g, up1_be, C2, 1.0f / M_u1);
    run_g32<true>(s_bufA, O_U1W2, up1_b2, s_b16, M_u1, C1, C2);

    // ---- skip1 MLP: concat(f1h, gather(b16, pool1)) ----
    cvt_kernel<<<512, 256>>>(f1, s_f1h, (long long)M_s1 * C1 / 4);
    zero_stats_kernel<<<4, 256>>>(1024);
    cvt_kernel<<<512, 256>>>(skip1_w1, s_wh + O_S1W1, (long long)(2 * C1) * (2 * C1) / 4);
    cvt_kernel<<<512, 256>>>(skip1_w2, s_wh + O_S1W2, (long long)(2 * C1) * C1 / 4);
    run_g16<true>(s_f1h, s_b16, pool1, N1, N2, O_S1W1, skip1_b1, s_bufA, M_s1, 2 * C1, 2 * C1);
    finalize_stats_kernel<<<4, 256>>>(skip1_g, skip1_be, 2 * C1, 1.0f / M_s1);
    run_g32<true>(s_bufA, O_S1W2, skip1_b2, s_b16, M_s1, C1, 2 * C1);

    // ---- up0 MLP: b16 (32768,512) -> 512 -> 256 ----
    zero_stats_kernel<<<2, 256>>>(512);
    cvt_kernel<<<256, 256>>>(up0_w1, s_wh + O_U0W1, (long long)C1 * C1 / 4);
    cvt_kernel<<<256, 256>>>(up0_w2, s_wh + O_U0W2, (long long)C1 * C0 / 4);
    run_g16<false>(s_b16, nullptr, nullptr, 1, 1, O_U0W1, up0_b1, s_bufA, M_s1, C1, C1);
    finalize_stats_kernel<<<2, 256>>>(up0_g, up0_be, C1, 1.0f / M_s1);
    run_g32<true>(s_bufA, O_U0W2, up0_b2, s_b16, M_s1, C0, C1);

    // ---- skip0 MLP: concat(f0h, gather(b16, pool0)) -> out ----
    cvt_kernel<<<1024, 256>>>(f0, s_f0h, (long long)M_s0 * C0 / 4);
    zero_stats_kernel<<<2, 256>>>(512);
    cvt_kernel<<<256, 256>>>(skip0_w1, s_wh + O_S0W1, (long long)(2 * C0) * (2 * C0) / 4);
    cvt_kernel<<<256, 256>>>(skip0_w2, s_wh + O_S0W2, (long long)(2 * C0) * C0 / 4);
    run_g16<true>(s_f0h, s_b16, pool0, N0, N1, O_S0W1, skip0_b1, s_bufA, M_s0, 2 * C0, 2 * C0);
    finalize_stats_kernel<<<2, 256>>>(skip0_g, skip0_be, 2 * C0, 1.0f / M_s0);
    run_g32<false>(s_bufA, O_S0W2, skip0_b2, out, M_s0, C0, 2 * C0);
}